// round 12
// baseline (speedup 1.0000x reference)
#include <cuda_runtime.h>
#include <cuda_fp16.h>
#include <cstdint>

#define L_SEQ   16384
#define D_MOD   1024
#define H_DIM   1024
#define T_CHUNK 128
#define N_CHUNK 128   // L_SEQ / T_CHUNK

// ---------------- static scratch ----------------
__device__ __half g_xh [(size_t)L_SEQ * D_MOD];          // fp16 x
__device__ __half g_W1h[(size_t)2 * H_DIM * D_MOD];      // [2048 x 1024] stacked re/im of scaled B
__device__ __half g_W2h[(size_t)D_MOD * 2 * H_DIM];      // [1024 x 2048] = [Cre | -Cim]
__device__ __half g_Buh[(size_t)L_SEQ * 2 * H_DIM];      // [16384 x 2048] Bu fp16 (scan input)
__device__ __half g_Hh [(size_t)L_SEQ * 2 * H_DIM];      // [16384 x 2048] hidden re|im (fp16)
__device__ float g_lre[H_DIM], g_lim[H_DIM];
__device__ float g_lTre[H_DIM], g_lTim[H_DIM];
__device__ float g_Ere[N_CHUNK * H_DIM], g_Eim[N_CHUNK * H_DIM];
__device__ float g_Sre[N_CHUNK * H_DIM], g_Sim[N_CHUNK * H_DIM];

// ---------------- helpers ----------------
__device__ __forceinline__ void cp16(uint32_t dst, const void* src) {
    asm volatile("cp.async.cg.shared.global [%0], [%1], 16;" :: "r"(dst), "l"(src) : "memory");
}
__device__ __forceinline__ void cp_commit() { asm volatile("cp.async.commit_group;" ::: "memory"); }
__device__ __forceinline__ void cp_wait1()  { asm volatile("cp.async.wait_group 1;" ::: "memory"); }
__device__ __forceinline__ void cp_wait0()  { asm volatile("cp.async.wait_group 0;" ::: "memory"); }
__device__ __forceinline__ uint32_t smem_u32(const void* p) {
    uint32_t a;
    asm("{ .reg .u64 t; cvta.to.shared.u64 t, %1; cvt.u32.u64 %0, t; }" : "=r"(a) : "l"(p));
    return a;
}
// fp16 HMMA, fp32 accumulate: 4 A regs (8 halves), 2 B regs (4 halves)
__device__ __forceinline__ void mma_f16(float* c, uint32_t a0, uint32_t a1, uint32_t a2, uint32_t a3,
                                        uint32_t b0, uint32_t b1) {
    asm volatile(
        "mma.sync.aligned.m16n8k16.row.col.f32.f16.f16.f32 "
        "{%0,%1,%2,%3}, {%4,%5,%6,%7}, {%8,%9}, {%0,%1,%2,%3};\n"
        : "+f"(c[0]), "+f"(c[1]), "+f"(c[2]), "+f"(c[3])
        : "r"(a0), "r"(a1), "r"(a2), "r"(a3), "r"(b0), "r"(b1));
}

// smem tile: 128 rows x 64 halves (= 32 b32), row stride 36 b32 (conflict-free: 36 ≡ 4 mod 32)
#define TSTRIDE   36                         // in b32 units
#define TILE_U32  (128 * TSTRIDE)            // 4608 b32 = 18432 B
#define STAGE_U32 (2 * TILE_U32)             // A tile + B tile = 36864 B
#define N_STAGES  3
#define SMEM_TOTAL (N_STAGES * STAGE_U32 * 4)  // 110592 B; x2 CTAs = 221KB <= 228KB/SM

// ---------------- FP16 NT GEMM: O[m,n] = sum_k A[m,k] * W[n,k]  (+ EPI: Dp[n]*X[m,n]) ----------------
// 128x128 block tile, BK=64 halves, 8 warps as 4(m) x 2(n); warp tile 32x64 -> mt=2, nt=8.
// 3-stage cp.async ring, ONE __syncthreads per chunk.
// K, offsets in HALF units.  OUTH=1: store __half2 into a half buffer; else float2.
template <int EPI, int OUTH>
__global__ __launch_bounds__(256, 2) void mma_gemm(
    const __half* __restrict__ A, const __half* __restrict__ W,
    void* __restrict__ O, int K, int Nout,
    const float* __restrict__ Dp, const float* __restrict__ X)
{
    extern __shared__ uint32_t smem[];
    const uint32_t sbase = smem_u32(smem);
    const int tid = threadIdx.x;
    const int wid = tid >> 5, lane = tid & 31;
    const int g = lane >> 2, tig = lane & 3;
    const int wm = wid & 3, wn = wid >> 2;           // 4 x 2 warps; warp tile 32 x 64
    const int m0 = blockIdx.x * 128, n0 = blockIdx.y * 128;
    const int NC = K >> 6;                           // K chunks of 64 halves

    const int r_ld  = tid >> 1;                      // 0..127 (row loaded by this thread)
    const int c4_ld = (tid & 1) * 4;                 // 16B-chunk index base (8 chunks per 128B row)

    auto load_chunk = [&](int stage, int kc) {
        const uint32_t sa = sbase + (uint32_t)(stage * STAGE_U32) * 4u;
        const uint32_t sb = sa + (uint32_t)TILE_U32 * 4u;
        const int kbase = kc * 64;                   // halves
#pragma unroll
        for (int i = 0; i < 4; i++) {
            int c4 = c4_ld + (i & 3);                // 0..7 (16B chunks)
            uint32_t doff = (uint32_t)(r_ld * TSTRIDE + c4 * 4) * 4u;
            cp16(sa + doff, A + (size_t)(m0 + r_ld) * K + kbase + c4 * 8);
            cp16(sb + doff, W + (size_t)(n0 + r_ld) * K + kbase + c4 * 8);
        }
    };

    float acc[2][8][4];
#pragma unroll
    for (int mt = 0; mt < 2; mt++)
#pragma unroll
        for (int nt = 0; nt < 8; nt++)
#pragma unroll
            for (int q = 0; q < 4; q++) acc[mt][nt][q] = 0.f;

    // prologue: two chunks in flight
    load_chunk(0, 0);
    cp_commit();
    load_chunk(1, 1);
    cp_commit();

    int stage = 0;
    for (int kc = 0; kc < NC; kc++) {
        cp_wait1();                 // pending = {kc, kc+1} -> oldest (kc) complete
        __syncthreads();            // all warps finished compute of kc-1 (stage reload target)
        if (kc + 2 < NC) {
            int ns = stage + 2; if (ns >= N_STAGES) ns -= N_STAGES;
            load_chunk(ns, kc + 2);
            cp_commit();
        }
        const uint32_t* As = smem + stage * STAGE_U32;
        const uint32_t* Bs = As + TILE_U32;
#pragma unroll
        for (int s = 0; s < 4; s++) {                // 4 k16-steps; each = 8 b32
            const int k0 = s * 8;                    // b32 units
            uint32_t af[2][4];
#pragma unroll
            for (int mt = 0; mt < 2; mt++) {
                int r = wm * 32 + mt * 16 + g;
                af[mt][0] = As[r * TSTRIDE + k0 + tig];
                af[mt][1] = As[(r + 8) * TSTRIDE + k0 + tig];
                af[mt][2] = As[r * TSTRIDE + k0 + tig + 4];
                af[mt][3] = As[(r + 8) * TSTRIDE + k0 + tig + 4];
            }
            uint32_t bf[8][2];
#pragma unroll
            for (int nt = 0; nt < 8; nt++) {
                int n = wn * 64 + nt * 8 + g;
                bf[nt][0] = Bs[n * TSTRIDE + k0 + tig];
                bf[nt][1] = Bs[n * TSTRIDE + k0 + tig + 4];
            }
#pragma unroll
            for (int mt = 0; mt < 2; mt++)
#pragma unroll
                for (int nt = 0; nt < 8; nt++)
                    mma_f16(acc[mt][nt], af[mt][0], af[mt][1], af[mt][2], af[mt][3],
                            bf[nt][0], bf[nt][1]);
        }
        if (++stage >= N_STAGES) stage = 0;
    }

    // epilogue
#pragma unroll
    for (int mt = 0; mt < 2; mt++) {
        int row0 = m0 + wm * 32 + mt * 16 + g;
#pragma unroll
        for (int nt = 0; nt < 8; nt++) {
            int col = n0 + wn * 64 + nt * 8 + tig * 2;
            float2 v0 = make_float2(acc[mt][nt][0], acc[mt][nt][1]);
            float2 v1 = make_float2(acc[mt][nt][2], acc[mt][nt][3]);
            if (EPI) {
                float2 dp = *(const float2*)(Dp + col);
                float2 x0 = *(const float2*)(X + (size_t)row0 * 1024 + col);
                float2 x1 = *(const float2*)(X + (size_t)(row0 + 8) * 1024 + col);
                v0.x += dp.x * x0.x; v0.y += dp.y * x0.y;
                v1.x += dp.x * x1.x; v1.y += dp.y * x1.y;
            }
            if (OUTH) {
                __half* Oh = (__half*)O;
                *(__half2*)(Oh + (size_t)row0 * Nout + col) = __floats2half2_rn(v0.x, v0.y);
                *(__half2*)(Oh + (size_t)(row0 + 8) * Nout + col) = __floats2half2_rn(v1.x, v1.y);
            } else {
                float* Of = (float*)O;
                *(float2*)(Of + (size_t)row0 * Nout + col) = v0;
                *(float2*)(Of + (size_t)(row0 + 8) * Nout + col) = v1;
            }
        }
    }
}

// ---------------- fused prep: conv_x | prep_W1 | prep_W2 | prep_params ----------------
#define NB_CONVX (L_SEQ * D_MOD / (256 * 4))   // 16384
#define NB_W1    (2 * H_DIM)                   // 2048
#define NB_W2    (D_MOD)                       // 1024
__global__ void prep_all(const float* __restrict__ x,
                         const float* __restrict__ Bre, const float* __restrict__ Bim,
                         const float* __restrict__ gamma_log,
                         const float* __restrict__ Cre, const float* __restrict__ Cim,
                         const float* __restrict__ nu_log, const float* __restrict__ theta_log) {
    int b = blockIdx.x;
    if (b < NB_CONVX) {
        size_t i = ((size_t)b * 256 + threadIdx.x) * 4;
        float4 v = *(const float4*)(x + i);
        g_xh[i + 0] = __float2half_rn(v.x);
        g_xh[i + 1] = __float2half_rn(v.y);
        g_xh[i + 2] = __float2half_rn(v.z);
        g_xh[i + 3] = __float2half_rn(v.w);
        return;
    }
    b -= NB_CONVX;
    if (b < NB_W1) {
        int n = b;                  // 0..2047
        int h = n & 1023;
        const float* src = (n < 1024) ? Bre : Bim;
        float eg = expf(gamma_log[h]);
#pragma unroll
        for (int j = 0; j < 4; j++) {
            int k = threadIdx.x * 4 + j;
            g_W1h[(size_t)n * 1024 + k] = __float2half_rn(src[h * 1024 + k] * eg);
        }
        return;
    }
    b -= NB_W1;
    if (b < NB_W2) {
        int n = b;                  // 0..1023
#pragma unroll
        for (int j = 0; j < 8; j++) {
            int k = threadIdx.x + j * 256;
            float v = (k < 1024) ? Cre[n * 1024 + k] : -Cim[n * 1024 + (k - 1024)];
            g_W2h[(size_t)n * 2048 + k] = __float2half_rn(v);
        }
        return;
    }
    b -= NB_W2;
    {   // prep_params: 4 blocks x 256 threads
        int h = b * 256 + threadIdx.x;
        if (h >= H_DIM) return;
        float nu = expf(nu_log[h]);
        float th = expf(theta_log[h]);
        float mag = expf(-nu);
        float lre = mag * cosf(th);
        float lim = mag * sinf(th);
        g_lre[h] = lre; g_lim[h] = lim;
        float ar = 1.f, ai = 0.f;
        for (int t = 0; t < T_CHUNK; t++) {
            float nr = ar * lre - ai * lim;
            ai = ar * lim + ai * lre;
            ar = nr;
        }
        g_lTre[h] = ar; g_lTim[h] = ai;
    }
}

// ---------------- scan (stacked [L x 2048]: re | im), 2 channels per thread ----------------
__global__ void scan_chunks() {
    int i = blockIdx.x * blockDim.x + threadIdx.x;   // channel pair 0..511
    int c = blockIdx.y;
    int h = i * 2;
    float2 lre = *(float2*)&g_lre[h];
    float2 lim = *(float2*)&g_lim[h];
    float hr0 = 0.f, hi0 = 0.f, hr1 = 0.f, hi1 = 0.f;
#pragma unroll 4
    for (int t = 0; t < T_CHUNK; t++) {
        size_t row = (size_t)(c * T_CHUNK + t) * 2048;
        float2 br = __half22float2(*(__half2*)&g_Buh[row + h]);
        float2 bi = __half22float2(*(__half2*)&g_Buh[row + 1024 + h]);
        float nr0 = fmaf(lre.x, hr0, fmaf(-lim.x, hi0, br.x));
        float ni0 = fmaf(lre.x, hi0, fmaf(lim.x, hr0, bi.x));
        float nr1 = fmaf(lre.y, hr1, fmaf(-lim.y, hi1, br.y));
        float ni1 = fmaf(lre.y, hi1, fmaf(lim.y, hr1, bi.y));
        hr0 = nr0; hi0 = ni0; hr1 = nr1; hi1 = ni1;
    }
    *(float2*)&g_Ere[c * H_DIM + h] = make_float2(hr0, hr1);
    *(float2*)&g_Eim[c * H_DIM + h] = make_float2(hi0, hi1);
}

__global__ void scan_combine(float* __restrict__ out_head, int head_mode) {
    int h = blockIdx.x * blockDim.x + threadIdx.x;
    float lTre = g_lTre[h], lTim = g_lTim[h];
    float sr = 0.f, si = 0.f;
#pragma unroll 4
    for (int c = 0; c < N_CHUNK; c++) {
        g_Sre[c * H_DIM + h] = sr;
        g_Sim[c * H_DIM + h] = si;
        float er = g_Ere[c * H_DIM + h];
        float ei = g_Eim[c * H_DIM + h];
        float nr = fmaf(lTre, sr, fmaf(-lTim, si, er));
        float ni = fmaf(lTre, si, fmaf(lTim, sr, ei));
        sr = nr; si = ni;
    }
    if (head_mode == 1) {
        out_head[h] = sr;
    } else if (head_mode == 2) {
        out_head[2 * h]     = sr;
        out_head[2 * h + 1] = si;
    }
}

__global__ void scan_apply() {      // emits fp16 hidden state into g_Hh
    int i = blockIdx.x * blockDim.x + threadIdx.x;   // channel pair 0..511
    int c = blockIdx.y;
    int h = i * 2;
    float2 lre = *(float2*)&g_lre[h];
    float2 lim = *(float2*)&g_lim[h];
    float2 sr = *(float2*)&g_Sre[c * H_DIM + h];
    float2 si = *(float2*)&g_Sim[c * H_DIM + h];
    float hr0 = sr.x, hi0 = si.x, hr1 = sr.y, hi1 = si.y;
#pragma unroll 4
    for (int t = 0; t < T_CHUNK; t++) {
        size_t row = (size_t)(c * T_CHUNK + t) * 2048;
        float2 br = __half22float2(*(__half2*)&g_Buh[row + h]);
        float2 bi = __half22float2(*(__half2*)&g_Buh[row + 1024 + h]);
        float nr0 = fmaf(lre.x, hr0, fmaf(-lim.x, hi0, br.x));
        float ni0 = fmaf(lre.x, hi0, fmaf(lim.x, hr0, bi.x));
        float nr1 = fmaf(lre.y, hr1, fmaf(-lim.y, hi1, br.y));
        float ni1 = fmaf(lre.y, hi1, fmaf(lim.y, hr1, bi.y));
        hr0 = nr0; hi0 = ni0; hr1 = nr1; hi1 = ni1;
        *(__half2*)&g_Hh[row + h]        = __floats2half2_rn(hr0, hr1);
        *(__half2*)&g_Hh[row + 1024 + h] = __floats2half2_rn(hi0, hi1);
    }
}

// ---------------- launch ----------------
extern "C" void kernel_launch(void* const* d_in, const int* in_sizes, int n_in,
                              void* d_out, int out_size) {
    const float* x         = (const float*)d_in[0];
    const float* nu_log    = (const float*)d_in[1];
    const float* theta_log = (const float*)d_in[2];
    const float* gamma_log = (const float*)d_in[3];
    const float* Bre       = (const float*)d_in[4];
    const float* Bim       = (const float*)d_in[5];
    const float* Cre       = (const float*)d_in[6];
    const float* Cim       = (const float*)d_in[7];
    const float* Dp        = (const float*)d_in[8];

    float* out = (float*)d_out;
    long long head = (long long)out_size - (long long)L_SEQ * D_MOD;
    if (head < 0) head = 0;
    int head_mode = 0;
    if (head >= 2 * H_DIM)  head_mode = 2;
    else if (head >= H_DIM) head_mode = 1;
    float* out_head = out;
    float* out_y = out + head;

    __half *pxh, *pW1h, *pW2h, *pHh, *pBuh;
    cudaGetSymbolAddress((void**)&pxh,  g_xh);
    cudaGetSymbolAddress((void**)&pW1h, g_W1h);
    cudaGetSymbolAddress((void**)&pW2h, g_W2h);
    cudaGetSymbolAddress((void**)&pHh,  g_Hh);
    cudaGetSymbolAddress((void**)&pBuh, g_Buh);

    cudaFuncSetAttribute((const void*)mma_gemm<0,1>, cudaFuncAttributeMaxDynamicSharedMemorySize, SMEM_TOTAL);
    cudaFuncSetAttribute((const void*)mma_gemm<1,0>, cudaFuncAttributeMaxDynamicSharedMemorySize, SMEM_TOTAL);

    prep_all<<<NB_CONVX + NB_W1 + NB_W2 + 4, 256>>>(
        x, Bre, Bim, gamma_log, Cre, Cim, nu_log, theta_log);

    // GEMM1: Bu[16384 x 2048] (fp16) = x @ [B'_re ; B'_im]^T   (K=1024 halves)
    mma_gemm<0,1><<<dim3(L_SEQ / 128, 2048 / 128), 256, SMEM_TOTAL>>>(
        pxh, pW1h, pBuh, 1024, 2048, nullptr, nullptr);

    scan_chunks<<<dim3(H_DIM / 512, N_CHUNK), 256>>>();
    scan_combine<<<H_DIM / 256, 256>>>(out_head, head_mode);
    scan_apply<<<dim3(H_DIM / 512, N_CHUNK), 256>>>();

    // GEMM2: y = [Hre|Him] @ [Cre|-Cim]^T + Dp*x   (K=2048 halves)
    mma_gemm<1,0><<<dim3(L_SEQ / 128, 1024 / 128), 256, SMEM_TOTAL>>>(
        pHh, pW2h, out_y, 2048, 1024, Dp, x);
}

// round 13
// speedup vs baseline: 1.0712x; 1.0712x over previous
#include <cuda_runtime.h>
#include <cuda_fp16.h>
#include <cstdint>

#define L_SEQ   16384
#define D_MOD   1024
#define H_DIM   1024
#define T_CHUNK 128
#define N_CHUNK 128   // L_SEQ / T_CHUNK

// ---------------- static scratch ----------------
__device__ __half g_xh [(size_t)L_SEQ * D_MOD];          // fp16 x
__device__ __half g_W1h[(size_t)2 * H_DIM * D_MOD];      // [2048 x 1024] stacked re/im of scaled B
__device__ __half g_W2h[(size_t)D_MOD * 2 * H_DIM];      // [1024 x 2048] = [Cre | -Cim]
__device__ __half g_Buh[(size_t)L_SEQ * 2 * H_DIM];      // [16384 x 2048] Bu fp16 (scan input)
__device__ __half g_Hh [(size_t)L_SEQ * 2 * H_DIM];      // [16384 x 2048] hidden re|im (fp16)
__device__ float g_lre[H_DIM], g_lim[H_DIM];
__device__ float g_lTre[H_DIM], g_lTim[H_DIM];
__device__ float g_Ere[N_CHUNK * H_DIM], g_Eim[N_CHUNK * H_DIM];
__device__ float g_Sre[N_CHUNK * H_DIM], g_Sim[N_CHUNK * H_DIM];

// ---------------- helpers ----------------
__device__ __forceinline__ void cp16(uint32_t dst, const void* src) {
    asm volatile("cp.async.cg.shared.global [%0], [%1], 16;" :: "r"(dst), "l"(src) : "memory");
}
__device__ __forceinline__ void cp_commit() { asm volatile("cp.async.commit_group;" ::: "memory"); }
__device__ __forceinline__ void cp_wait1()  { asm volatile("cp.async.wait_group 1;" ::: "memory"); }
__device__ __forceinline__ void cp_wait0()  { asm volatile("cp.async.wait_group 0;" ::: "memory"); }
__device__ __forceinline__ uint32_t smem_u32(const void* p) {
    uint32_t a;
    asm("{ .reg .u64 t; cvta.to.shared.u64 t, %1; cvt.u32.u64 %0, t; }" : "=r"(a) : "l"(p));
    return a;
}
// fp16 HMMA, fp32 accumulate: 4 A regs (8 halves), 2 B regs (4 halves)
__device__ __forceinline__ void mma_f16(float* c, uint32_t a0, uint32_t a1, uint32_t a2, uint32_t a3,
                                        uint32_t b0, uint32_t b1) {
    asm volatile(
        "mma.sync.aligned.m16n8k16.row.col.f32.f16.f16.f32 "
        "{%0,%1,%2,%3}, {%4,%5,%6,%7}, {%8,%9}, {%0,%1,%2,%3};\n"
        : "+f"(c[0]), "+f"(c[1]), "+f"(c[2]), "+f"(c[3])
        : "r"(a0), "r"(a1), "r"(a2), "r"(a3), "r"(b0), "r"(b1));
}

// smem tile: 128 rows x 64 halves (= 32 b32), row stride 36 b32 (conflict-free: 36 ≡ 4 mod 32)
#define TSTRIDE   36                         // in b32 units
#define TILE_U32  (128 * TSTRIDE)            // 4608 b32 = 18432 B
#define STAGE_U32 (2 * TILE_U32)             // A tile + B tile
#define SMEM_TOTAL (2 * STAGE_U32 * 4)       // double buffered = 73728 B

// ---------------- FP16 NT GEMM: O[m,n] = sum_k A[m,k] * W[n,k]  (+ EPI: Dp[n]*X[m,n]) ----------------
// 128x128 block tile, BK=64 halves, 8 warps as 4(m) x 2(n); warp tile 32x64 -> mt=2, nt=8.
// R9's proven 2-stage double buffer.  K, offsets in HALF units.
// OUTH=1: store __half2 into a half buffer; else float2.
template <int EPI, int OUTH>
__global__ __launch_bounds__(256, 2) void mma_gemm(
    const __half* __restrict__ A, const __half* __restrict__ W,
    void* __restrict__ O, int K, int Nout,
    const float* __restrict__ Dp, const float* __restrict__ X)
{
    extern __shared__ uint32_t smem[];
    const uint32_t sbase = smem_u32(smem);
    const int tid = threadIdx.x;
    const int wid = tid >> 5, lane = tid & 31;
    const int g = lane >> 2, tig = lane & 3;
    const int wm = wid & 3, wn = wid >> 2;           // 4 x 2 warps; warp tile 32 x 64
    const int m0 = blockIdx.x * 128, n0 = blockIdx.y * 128;
    const int NC = K >> 6;                           // K chunks of 64 halves

    const int r_ld  = tid >> 1;                      // 0..127 (row loaded by this thread)
    const int c4_ld = (tid & 1) * 4;                 // 16B-chunk index base (8 chunks per 128B row)

    auto load_chunk = [&](int stage, int kc) {
        const uint32_t sa = sbase + (uint32_t)(stage * STAGE_U32) * 4u;
        const uint32_t sb = sa + (uint32_t)TILE_U32 * 4u;
        const int kbase = kc * 64;                   // halves
#pragma unroll
        for (int i = 0; i < 4; i++) {
            int c4 = c4_ld + (i & 3);                // 0..7 (16B chunks)
            uint32_t doff = (uint32_t)(r_ld * TSTRIDE + c4 * 4) * 4u;
            cp16(sa + doff, A + (size_t)(m0 + r_ld) * K + kbase + c4 * 8);
            cp16(sb + doff, W + (size_t)(n0 + r_ld) * K + kbase + c4 * 8);
        }
    };

    float acc[2][8][4];
#pragma unroll
    for (int mt = 0; mt < 2; mt++)
#pragma unroll
        for (int nt = 0; nt < 8; nt++)
#pragma unroll
            for (int q = 0; q < 4; q++) acc[mt][nt][q] = 0.f;

    load_chunk(0, 0);
    cp_commit();

    for (int kc = 0; kc < NC; kc++) {
        if (kc + 1 < NC) {
            load_chunk((kc + 1) & 1, kc + 1);
            cp_commit();
            cp_wait1();
        } else {
            cp_wait0();
        }
        __syncthreads();
        const uint32_t* As = smem + (kc & 1) * STAGE_U32;
        const uint32_t* Bs = As + TILE_U32;
#pragma unroll
        for (int s = 0; s < 4; s++) {                // 4 k16-steps; each = 8 b32
            const int k0 = s * 8;                    // b32 units
            uint32_t af[2][4];
#pragma unroll
            for (int mt = 0; mt < 2; mt++) {
                int r = wm * 32 + mt * 16 + g;
                af[mt][0] = As[r * TSTRIDE + k0 + tig];
                af[mt][1] = As[(r + 8) * TSTRIDE + k0 + tig];
                af[mt][2] = As[r * TSTRIDE + k0 + tig + 4];
                af[mt][3] = As[(r + 8) * TSTRIDE + k0 + tig + 4];
            }
            uint32_t bf[8][2];
#pragma unroll
            for (int nt = 0; nt < 8; nt++) {
                int n = wn * 64 + nt * 8 + g;
                bf[nt][0] = Bs[n * TSTRIDE + k0 + tig];
                bf[nt][1] = Bs[n * TSTRIDE + k0 + tig + 4];
            }
#pragma unroll
            for (int mt = 0; mt < 2; mt++)
#pragma unroll
                for (int nt = 0; nt < 8; nt++)
                    mma_f16(acc[mt][nt], af[mt][0], af[mt][1], af[mt][2], af[mt][3],
                            bf[nt][0], bf[nt][1]);
        }
        __syncthreads();
    }

    // epilogue
#pragma unroll
    for (int mt = 0; mt < 2; mt++) {
        int row0 = m0 + wm * 32 + mt * 16 + g;
#pragma unroll
        for (int nt = 0; nt < 8; nt++) {
            int col = n0 + wn * 64 + nt * 8 + tig * 2;
            float2 v0 = make_float2(acc[mt][nt][0], acc[mt][nt][1]);
            float2 v1 = make_float2(acc[mt][nt][2], acc[mt][nt][3]);
            if (EPI) {
                float2 dp = *(const float2*)(Dp + col);
                float2 x0 = *(const float2*)(X + (size_t)row0 * 1024 + col);
                float2 x1 = *(const float2*)(X + (size_t)(row0 + 8) * 1024 + col);
                v0.x += dp.x * x0.x; v0.y += dp.y * x0.y;
                v1.x += dp.x * x1.x; v1.y += dp.y * x1.y;
            }
            if (OUTH) {
                __half* Oh = (__half*)O;
                *(__half2*)(Oh + (size_t)row0 * Nout + col) = __floats2half2_rn(v0.x, v0.y);
                *(__half2*)(Oh + (size_t)(row0 + 8) * Nout + col) = __floats2half2_rn(v1.x, v1.y);
            } else {
                float* Of = (float*)O;
                *(float2*)(Of + (size_t)row0 * Nout + col) = v0;
                *(float2*)(Of + (size_t)(row0 + 8) * Nout + col) = v1;
            }
        }
    }
}

// ---------------- fused prep: conv_x | prep_W1 | prep_W2 | prep_params ----------------
#define NB_CONVX (L_SEQ * D_MOD / (256 * 4))   // 16384
#define NB_W1    (2 * H_DIM)                   // 2048
#define NB_W2    (D_MOD)                       // 1024
__global__ void prep_all(const float* __restrict__ x,
                         const float* __restrict__ Bre, const float* __restrict__ Bim,
                         const float* __restrict__ gamma_log,
                         const float* __restrict__ Cre, const float* __restrict__ Cim,
                         const float* __restrict__ nu_log, const float* __restrict__ theta_log) {
    int b = blockIdx.x;
    if (b < NB_CONVX) {
        size_t i = ((size_t)b * 256 + threadIdx.x) * 4;
        float4 v = *(const float4*)(x + i);
        g_xh[i + 0] = __float2half_rn(v.x);
        g_xh[i + 1] = __float2half_rn(v.y);
        g_xh[i + 2] = __float2half_rn(v.z);
        g_xh[i + 3] = __float2half_rn(v.w);
        return;
    }
    b -= NB_CONVX;
    if (b < NB_W1) {
        int n = b;                  // 0..2047
        int h = n & 1023;
        const float* src = (n < 1024) ? Bre : Bim;
        float eg = expf(gamma_log[h]);
#pragma unroll
        for (int j = 0; j < 4; j++) {
            int k = threadIdx.x * 4 + j;
            g_W1h[(size_t)n * 1024 + k] = __float2half_rn(src[h * 1024 + k] * eg);
        }
        return;
    }
    b -= NB_W1;
    if (b < NB_W2) {
        int n = b;                  // 0..1023
#pragma unroll
        for (int j = 0; j < 8; j++) {
            int k = threadIdx.x + j * 256;
            float v = (k < 1024) ? Cre[n * 1024 + k] : -Cim[n * 1024 + (k - 1024)];
            g_W2h[(size_t)n * 2048 + k] = __float2half_rn(v);
        }
        return;
    }
    b -= NB_W2;
    {   // prep_params: 4 blocks x 256 threads
        int h = b * 256 + threadIdx.x;
        if (h >= H_DIM) return;
        float nu = expf(nu_log[h]);
        float th = expf(theta_log[h]);
        float mag = expf(-nu);
        float lre = mag * cosf(th);
        float lim = mag * sinf(th);
        g_lre[h] = lre; g_lim[h] = lim;
        float ar = 1.f, ai = 0.f;
        for (int t = 0; t < T_CHUNK; t++) {
            float nr = ar * lre - ai * lim;
            ai = ar * lim + ai * lre;
            ar = nr;
        }
        g_lTre[h] = ar; g_lTim[h] = ai;
    }
}

// ---------------- scan (stacked [L x 2048]: re | im), 2 channels per thread ----------------
__global__ void scan_chunks() {
    int i = blockIdx.x * blockDim.x + threadIdx.x;   // channel pair 0..511
    int c = blockIdx.y;
    int h = i * 2;
    float2 lre = *(float2*)&g_lre[h];
    float2 lim = *(float2*)&g_lim[h];
    float hr0 = 0.f, hi0 = 0.f, hr1 = 0.f, hi1 = 0.f;
#pragma unroll 4
    for (int t = 0; t < T_CHUNK; t++) {
        size_t row = (size_t)(c * T_CHUNK + t) * 2048;
        float2 br = __half22float2(*(__half2*)&g_Buh[row + h]);
        float2 bi = __half22float2(*(__half2*)&g_Buh[row + 1024 + h]);
        float nr0 = fmaf(lre.x, hr0, fmaf(-lim.x, hi0, br.x));
        float ni0 = fmaf(lre.x, hi0, fmaf(lim.x, hr0, bi.x));
        float nr1 = fmaf(lre.y, hr1, fmaf(-lim.y, hi1, br.y));
        float ni1 = fmaf(lre.y, hi1, fmaf(lim.y, hr1, bi.y));
        hr0 = nr0; hi0 = ni0; hr1 = nr1; hi1 = ni1;
    }
    *(float2*)&g_Ere[c * H_DIM + h] = make_float2(hr0, hr1);
    *(float2*)&g_Eim[c * H_DIM + h] = make_float2(hi0, hi1);
}

// ---------------- cross-chunk scan: warp-parallel Kogge-Stone, one warp per channel ----------------
__global__ void scan_combine(float* __restrict__ out_head, int head_mode) {
    int h    = (blockIdx.x * blockDim.x + threadIdx.x) >> 5;  // channel = warp id
    int lane = threadIdx.x & 31;
    float Ar = g_lTre[h], Ai = g_lTim[h];      // λ^T_CHUNK (per-chunk multiplier)

    // local fold of 4 chunks (c = lane*4 + j): inclusive b over own segment
    float br = 0.f, bi = 0.f;
#pragma unroll
    for (int j = 0; j < 4; j++) {
        int c = lane * 4 + j;
        float er = g_Ere[c * H_DIM + h];
        float ei = g_Eim[c * H_DIM + h];
        float nr = fmaf(Ar, br, fmaf(-Ai, bi, er));
        float ni = fmaf(Ar, bi, fmaf(Ai, br, ei));
        br = nr; bi = ni;
    }
    // segment operator A_seg = λT^4 (two squarings)
    float A2r = Ar * Ar - Ai * Ai, A2i = 2.f * Ar * Ai;
    float sAr = A2r * A2r - A2i * A2i, sAi = 2.f * A2r * A2i;

    // Kogge-Stone inclusive scan over lanes with op (A_j*A_i, A_j*b_i + b_j)
#pragma unroll
    for (int d = 1; d < 32; d <<= 1) {
        float pAr = __shfl_up_sync(0xffffffffu, sAr, d);
        float pAi = __shfl_up_sync(0xffffffffu, sAi, d);
        float pbr = __shfl_up_sync(0xffffffffu, br, d);
        float pbi = __shfl_up_sync(0xffffffffu, bi, d);
        if (lane >= d) {
            float nbr = fmaf(sAr, pbr, fmaf(-sAi, pbi, br));
            float nbi = fmaf(sAr, pbi, fmaf(sAi, pbr, bi));
            br = nbr; bi = nbi;
            float nAr = sAr * pAr - sAi * pAi;
            float nAi = sAr * pAi + sAi * pAr;
            sAr = nAr; sAi = nAi;
        }
    }

    // exclusive handoff: state entering this lane's segment = inclusive of lane-1
    float s0r = __shfl_up_sync(0xffffffffu, br, 1);
    float s0i = __shfl_up_sync(0xffffffffu, bi, 1);
    if (lane == 0) { s0r = 0.f; s0i = 0.f; }

    float sr = s0r, si = s0i;
#pragma unroll
    for (int j = 0; j < 4; j++) {
        int c = lane * 4 + j;
        g_Sre[c * H_DIM + h] = sr;
        g_Sim[c * H_DIM + h] = si;
        float er = g_Ere[c * H_DIM + h];
        float ei = g_Eim[c * H_DIM + h];
        float nr = fmaf(Ar, sr, fmaf(-Ai, si, er));
        float ni = fmaf(Ar, si, fmaf(Ai, sr, ei));
        sr = nr; si = ni;
    }
    if (lane == 31) {               // final state = hidden[-1]
        if (head_mode == 1) {
            out_head[h] = sr;
        } else if (head_mode == 2) {
            out_head[2 * h]     = sr;
            out_head[2 * h + 1] = si;
        }
    }
}

__global__ void scan_apply() {      // emits fp16 hidden state into g_Hh
    int i = blockIdx.x * blockDim.x + threadIdx.x;   // channel pair 0..511
    int c = blockIdx.y;
    int h = i * 2;
    float2 lre = *(float2*)&g_lre[h];
    float2 lim = *(float2*)&g_lim[h];
    float2 sr = *(float2*)&g_Sre[c * H_DIM + h];
    float2 si = *(float2*)&g_Sim[c * H_DIM + h];
    float hr0 = sr.x, hi0 = si.x, hr1 = sr.y, hi1 = si.y;
#pragma unroll 4
    for (int t = 0; t < T_CHUNK; t++) {
        size_t row = (size_t)(c * T_CHUNK + t) * 2048;
        float2 br = __half22float2(*(__half2*)&g_Buh[row + h]);
        float2 bi = __half22float2(*(__half2*)&g_Buh[row + 1024 + h]);
        float nr0 = fmaf(lre.x, hr0, fmaf(-lim.x, hi0, br.x));
        float ni0 = fmaf(lre.x, hi0, fmaf(lim.x, hr0, bi.x));
        float nr1 = fmaf(lre.y, hr1, fmaf(-lim.y, hi1, br.y));
        float ni1 = fmaf(lre.y, hi1, fmaf(lim.y, hr1, bi.y));
        hr0 = nr0; hi0 = ni0; hr1 = nr1; hi1 = ni1;
        *(__half2*)&g_Hh[row + h]        = __floats2half2_rn(hr0, hr1);
        *(__half2*)&g_Hh[row + 1024 + h] = __floats2half2_rn(hi0, hi1);
    }
}

// ---------------- launch ----------------
extern "C" void kernel_launch(void* const* d_in, const int* in_sizes, int n_in,
                              void* d_out, int out_size) {
    const float* x         = (const float*)d_in[0];
    const float* nu_log    = (const float*)d_in[1];
    const float* theta_log = (const float*)d_in[2];
    const float* gamma_log = (const float*)d_in[3];
    const float* Bre       = (const float*)d_in[4];
    const float* Bim       = (const float*)d_in[5];
    const float* Cre       = (const float*)d_in[6];
    const float* Cim       = (const float*)d_in[7];
    const float* Dp        = (const float*)d_in[8];

    float* out = (float*)d_out;
    long long head = (long long)out_size - (long long)L_SEQ * D_MOD;
    if (head < 0) head = 0;
    int head_mode = 0;
    if (head >= 2 * H_DIM)  head_mode = 2;
    else if (head >= H_DIM) head_mode = 1;
    float* out_head = out;
    float* out_y = out + head;

    __half *pxh, *pW1h, *pW2h, *pHh, *pBuh;
    cudaGetSymbolAddress((void**)&pxh,  g_xh);
    cudaGetSymbolAddress((void**)&pW1h, g_W1h);
    cudaGetSymbolAddress((void**)&pW2h, g_W2h);
    cudaGetSymbolAddress((void**)&pHh,  g_Hh);
    cudaGetSymbolAddress((void**)&pBuh, g_Buh);

    cudaFuncSetAttribute((const void*)mma_gemm<0,1>, cudaFuncAttributeMaxDynamicSharedMemorySize, SMEM_TOTAL);
    cudaFuncSetAttribute((const void*)mma_gemm<1,0>, cudaFuncAttributeMaxDynamicSharedMemorySize, SMEM_TOTAL);

    prep_all<<<NB_CONVX + NB_W1 + NB_W2 + 4, 256>>>(
        x, Bre, Bim, gamma_log, Cre, Cim, nu_log, theta_log);

    // GEMM1: Bu[16384 x 2048] (fp16) = x @ [B'_re ; B'_im]^T   (K=1024 halves)
    mma_gemm<0,1><<<dim3(L_SEQ / 128, 2048 / 128), 256, SMEM_TOTAL>>>(
        pxh, pW1h, pBuh, 1024, 2048, nullptr, nullptr);

    scan_chunks<<<dim3(H_DIM / 512, N_CHUNK), 256>>>();
    scan_combine<<<(H_DIM * 32) / 256, 256>>>(out_head, head_mode);   // 1 warp per channel
    scan_apply<<<dim3(H_DIM / 512, N_CHUNK), 256>>>();

    // GEMM2: y = [Hre|Him] @ [Cre|-Cim]^T + Dp*x   (K=2048 halves)
    mma_gemm<1,0><<<dim3(L_SEQ / 128, 1024 / 128), 256, SMEM_TOTAL>>>(
        pHh, pW2h, out_y, 2048, 1024, Dp, x);
}

// round 14
// speedup vs baseline: 1.0716x; 1.0003x over previous
#include <cuda_runtime.h>
#include <cuda_fp16.h>
#include <cstdint>

#define L_SEQ   16384
#define D_MOD   1024
#define H_DIM   1024
#define T_CHUNK 128
#define N_CHUNK 128   // L_SEQ / T_CHUNK

// ---------------- static scratch ----------------
__device__ __half g_xh [(size_t)L_SEQ * D_MOD];          // fp16 x
__device__ __half g_W1h[(size_t)2 * H_DIM * D_MOD];      // [2048 x 1024] stacked re/im of scaled B
__device__ __half g_W2h[(size_t)D_MOD * 2 * H_DIM];      // [1024 x 2048] = [Cre | -Cim]
__device__ __half g_Buh[(size_t)L_SEQ * 2 * H_DIM];      // [16384 x 2048] Bu fp16 (scan input)
__device__ __half g_Hh [(size_t)L_SEQ * 2 * H_DIM];      // [16384 x 2048] hidden re|im (fp16)
__device__ float g_lre[H_DIM], g_lim[H_DIM];
__device__ float g_lTre[H_DIM], g_lTim[H_DIM];
__device__ float g_Ere[N_CHUNK * H_DIM], g_Eim[N_CHUNK * H_DIM];
__device__ float g_Sre[N_CHUNK * H_DIM], g_Sim[N_CHUNK * H_DIM];

// ---------------- helpers ----------------
__device__ __forceinline__ void cp16(uint32_t dst, const void* src) {
    asm volatile("cp.async.cg.shared.global [%0], [%1], 16;" :: "r"(dst), "l"(src) : "memory");
}
__device__ __forceinline__ void cp_commit() { asm volatile("cp.async.commit_group;" ::: "memory"); }
__device__ __forceinline__ void cp_wait1()  { asm volatile("cp.async.wait_group 1;" ::: "memory"); }
__device__ __forceinline__ void cp_wait0()  { asm volatile("cp.async.wait_group 0;" ::: "memory"); }
__device__ __forceinline__ uint32_t smem_u32(const void* p) {
    uint32_t a;
    asm("{ .reg .u64 t; cvta.to.shared.u64 t, %1; cvt.u32.u64 %0, t; }" : "=r"(a) : "l"(p));
    return a;
}
// fp16 HMMA, fp32 accumulate: 4 A regs (8 halves), 2 B regs (4 halves)
__device__ __forceinline__ void mma_f16(float* c, uint32_t a0, uint32_t a1, uint32_t a2, uint32_t a3,
                                        uint32_t b0, uint32_t b1) {
    asm volatile(
        "mma.sync.aligned.m16n8k16.row.col.f32.f16.f16.f32 "
        "{%0,%1,%2,%3}, {%4,%5,%6,%7}, {%8,%9}, {%0,%1,%2,%3};\n"
        : "+f"(c[0]), "+f"(c[1]), "+f"(c[2]), "+f"(c[3])
        : "r"(a0), "r"(a1), "r"(a2), "r"(a3), "r"(b0), "r"(b1));
}

// smem tile: 128 rows x 64 halves (= 32 b32), row stride 36 b32 (conflict-free: 36 ≡ 4 mod 32)
#define TSTRIDE   36                         // in b32 units
#define TILE_U32  (128 * TSTRIDE)            // 4608 b32 = 18432 B
#define STAGE_U32 (2 * TILE_U32)             // A tile + B tile
#define SMEM_TOTAL (2 * STAGE_U32 * 4)       // double buffered = 73728 B

// ---------------- FP16 NT GEMM: O[m,n] = sum_k A[m,k] * W[n,k]  (+ EPI: Dp[n]*X[m,n]) ----------------
// 128x128 block tile, BK=64 halves, 8 warps as 4(m) x 2(n); warp tile 32x64 -> mt=2, nt=8.
// R9's proven 2-stage double buffer.  K, offsets in HALF units.
// OUTH=1: store __half2 into a half buffer; else float2.
template <int EPI, int OUTH>
__global__ __launch_bounds__(256, 2) void mma_gemm(
    const __half* __restrict__ A, const __half* __restrict__ W,
    void* __restrict__ O, int K, int Nout,
    const float* __restrict__ Dp, const float* __restrict__ X)
{
    extern __shared__ uint32_t smem[];
    const uint32_t sbase = smem_u32(smem);
    const int tid = threadIdx.x;
    const int wid = tid >> 5, lane = tid & 31;
    const int g = lane >> 2, tig = lane & 3;
    const int wm = wid & 3, wn = wid >> 2;           // 4 x 2 warps; warp tile 32 x 64
    const int m0 = blockIdx.x * 128, n0 = blockIdx.y * 128;
    const int NC = K >> 6;                           // K chunks of 64 halves

    const int r_ld  = tid >> 1;                      // 0..127 (row loaded by this thread)
    const int c4_ld = (tid & 1) * 4;                 // 16B-chunk index base (8 chunks per 128B row)

    auto load_chunk = [&](int stage, int kc) {
        const uint32_t sa = sbase + (uint32_t)(stage * STAGE_U32) * 4u;
        const uint32_t sb = sa + (uint32_t)TILE_U32 * 4u;
        const int kbase = kc * 64;                   // halves
#pragma unroll
        for (int i = 0; i < 4; i++) {
            int c4 = c4_ld + (i & 3);                // 0..7 (16B chunks)
            uint32_t doff = (uint32_t)(r_ld * TSTRIDE + c4 * 4) * 4u;
            cp16(sa + doff, A + (size_t)(m0 + r_ld) * K + kbase + c4 * 8);
            cp16(sb + doff, W + (size_t)(n0 + r_ld) * K + kbase + c4 * 8);
        }
    };

    float acc[2][8][4];
#pragma unroll
    for (int mt = 0; mt < 2; mt++)
#pragma unroll
        for (int nt = 0; nt < 8; nt++)
#pragma unroll
            for (int q = 0; q < 4; q++) acc[mt][nt][q] = 0.f;

    load_chunk(0, 0);
    cp_commit();

    for (int kc = 0; kc < NC; kc++) {
        if (kc + 1 < NC) {
            load_chunk((kc + 1) & 1, kc + 1);
            cp_commit();
            cp_wait1();
        } else {
            cp_wait0();
        }
        __syncthreads();
        const uint32_t* As = smem + (kc & 1) * STAGE_U32;
        const uint32_t* Bs = As + TILE_U32;
#pragma unroll
        for (int s = 0; s < 4; s++) {                // 4 k16-steps; each = 8 b32
            const int k0 = s * 8;                    // b32 units
            uint32_t af[2][4];
#pragma unroll
            for (int mt = 0; mt < 2; mt++) {
                int r = wm * 32 + mt * 16 + g;
                af[mt][0] = As[r * TSTRIDE + k0 + tig];
                af[mt][1] = As[(r + 8) * TSTRIDE + k0 + tig];
                af[mt][2] = As[r * TSTRIDE + k0 + tig + 4];
                af[mt][3] = As[(r + 8) * TSTRIDE + k0 + tig + 4];
            }
            uint32_t bf[8][2];
#pragma unroll
            for (int nt = 0; nt < 8; nt++) {
                int n = wn * 64 + nt * 8 + g;
                bf[nt][0] = Bs[n * TSTRIDE + k0 + tig];
                bf[nt][1] = Bs[n * TSTRIDE + k0 + tig + 4];
            }
#pragma unroll
            for (int mt = 0; mt < 2; mt++)
#pragma unroll
                for (int nt = 0; nt < 8; nt++)
                    mma_f16(acc[mt][nt], af[mt][0], af[mt][1], af[mt][2], af[mt][3],
                            bf[nt][0], bf[nt][1]);
        }
        __syncthreads();
    }

    // epilogue
#pragma unroll
    for (int mt = 0; mt < 2; mt++) {
        int row0 = m0 + wm * 32 + mt * 16 + g;
#pragma unroll
        for (int nt = 0; nt < 8; nt++) {
            int col = n0 + wn * 64 + nt * 8 + tig * 2;
            float2 v0 = make_float2(acc[mt][nt][0], acc[mt][nt][1]);
            float2 v1 = make_float2(acc[mt][nt][2], acc[mt][nt][3]);
            if (EPI) {
                float2 dp = *(const float2*)(Dp + col);
                float2 x0 = *(const float2*)(X + (size_t)row0 * 1024 + col);
                float2 x1 = *(const float2*)(X + (size_t)(row0 + 8) * 1024 + col);
                v0.x += dp.x * x0.x; v0.y += dp.y * x0.y;
                v1.x += dp.x * x1.x; v1.y += dp.y * x1.y;
            }
            if (OUTH) {
                __half* Oh = (__half*)O;
                *(__half2*)(Oh + (size_t)row0 * Nout + col) = __floats2half2_rn(v0.x, v0.y);
                *(__half2*)(Oh + (size_t)(row0 + 8) * Nout + col) = __floats2half2_rn(v1.x, v1.y);
            } else {
                float* Of = (float*)O;
                *(float2*)(Of + (size_t)row0 * Nout + col) = v0;
                *(float2*)(Of + (size_t)(row0 + 8) * Nout + col) = v1;
            }
        }
    }
}

// ---------------- prep kernels (split so GEMM1 is the 4th launch for ncu capture) ----------------
// launch #1: params + W2
__global__ void prep_small(const float* __restrict__ Cre, const float* __restrict__ Cim,
                           const float* __restrict__ nu_log, const float* __restrict__ theta_log) {
    int b = blockIdx.x;
    if (b < D_MOD) {                 // W2 rows
        int n = b;
#pragma unroll
        for (int j = 0; j < 8; j++) {
            int k = threadIdx.x + j * 256;
            float v = (k < 1024) ? Cre[n * 1024 + k] : -Cim[n * 1024 + (k - 1024)];
            g_W2h[(size_t)n * 2048 + k] = __float2half_rn(v);
        }
        return;
    }
    b -= D_MOD;
    {   // params: 4 blocks
        int h = b * 256 + threadIdx.x;
        if (h >= H_DIM) return;
        float nu = expf(nu_log[h]);
        float th = expf(theta_log[h]);
        float mag = expf(-nu);
        float lre = mag * cosf(th);
        float lim = mag * sinf(th);
        g_lre[h] = lre; g_lim[h] = lim;
        float ar = 1.f, ai = 0.f;
        for (int t = 0; t < T_CHUNK; t++) {
            float nr = ar * lre - ai * lim;
            ai = ar * lim + ai * lre;
            ar = nr;
        }
        g_lTre[h] = ar; g_lTim[h] = ai;
    }
}

// launch #2: W1
__global__ void prep_W1k(const float* __restrict__ Bre, const float* __restrict__ Bim,
                         const float* __restrict__ gamma_log) {
    int n = blockIdx.x;             // 0..2047
    int h = n & 1023;
    const float* src = (n < 1024) ? Bre : Bim;
    float eg = expf(gamma_log[h]);
#pragma unroll
    for (int j = 0; j < 4; j++) {
        int k = threadIdx.x * 4 + j;
        g_W1h[(size_t)n * 1024 + k] = __float2half_rn(src[h * 1024 + k] * eg);
    }
}

// launch #3: x -> fp16
__global__ void conv_x(const float* __restrict__ x) {
    size_t i = (size_t)(blockIdx.x * blockDim.x + threadIdx.x) * 4;
    float4 v = *(const float4*)(x + i);
    g_xh[i + 0] = __float2half_rn(v.x);
    g_xh[i + 1] = __float2half_rn(v.y);
    g_xh[i + 2] = __float2half_rn(v.z);
    g_xh[i + 3] = __float2half_rn(v.w);
}

// ---------------- scan (stacked [L x 2048]: re | im), 2 channels per thread ----------------
__global__ void scan_chunks() {
    int i = blockIdx.x * blockDim.x + threadIdx.x;   // channel pair 0..511
    int c = blockIdx.y;
    int h = i * 2;
    float2 lre = *(float2*)&g_lre[h];
    float2 lim = *(float2*)&g_lim[h];
    float hr0 = 0.f, hi0 = 0.f, hr1 = 0.f, hi1 = 0.f;
#pragma unroll 4
    for (int t = 0; t < T_CHUNK; t++) {
        size_t row = (size_t)(c * T_CHUNK + t) * 2048;
        float2 br = __half22float2(*(__half2*)&g_Buh[row + h]);
        float2 bi = __half22float2(*(__half2*)&g_Buh[row + 1024 + h]);
        float nr0 = fmaf(lre.x, hr0, fmaf(-lim.x, hi0, br.x));
        float ni0 = fmaf(lre.x, hi0, fmaf(lim.x, hr0, bi.x));
        float nr1 = fmaf(lre.y, hr1, fmaf(-lim.y, hi1, br.y));
        float ni1 = fmaf(lre.y, hi1, fmaf(lim.y, hr1, bi.y));
        hr0 = nr0; hi0 = ni0; hr1 = nr1; hi1 = ni1;
    }
    *(float2*)&g_Ere[c * H_DIM + h] = make_float2(hr0, hr1);
    *(float2*)&g_Eim[c * H_DIM + h] = make_float2(hi0, hi1);
}

// ---------------- cross-chunk scan: warp-parallel Kogge-Stone, one warp per channel ----------------
__global__ void scan_combine(float* __restrict__ out_head, int head_mode) {
    int h    = (blockIdx.x * blockDim.x + threadIdx.x) >> 5;  // channel = warp id
    int lane = threadIdx.x & 31;
    float Ar = g_lTre[h], Ai = g_lTim[h];      // λ^T_CHUNK (per-chunk multiplier)

    // local fold of 4 chunks (c = lane*4 + j): inclusive b over own segment
    float br = 0.f, bi = 0.f;
#pragma unroll
    for (int j = 0; j < 4; j++) {
        int c = lane * 4 + j;
        float er = g_Ere[c * H_DIM + h];
        float ei = g_Eim[c * H_DIM + h];
        float nr = fmaf(Ar, br, fmaf(-Ai, bi, er));
        float ni = fmaf(Ar, bi, fmaf(Ai, br, ei));
        br = nr; bi = ni;
    }
    // segment operator A_seg = λT^4 (two squarings)
    float A2r = Ar * Ar - Ai * Ai, A2i = 2.f * Ar * Ai;
    float sAr = A2r * A2r - A2i * A2i, sAi = 2.f * A2r * A2i;

    // Kogge-Stone inclusive scan over lanes with op (A_j*A_i, A_j*b_i + b_j)
#pragma unroll
    for (int d = 1; d < 32; d <<= 1) {
        float pAr = __shfl_up_sync(0xffffffffu, sAr, d);
        float pAi = __shfl_up_sync(0xffffffffu, sAi, d);
        float pbr = __shfl_up_sync(0xffffffffu, br, d);
        float pbi = __shfl_up_sync(0xffffffffu, bi, d);
        if (lane >= d) {
            float nbr = fmaf(sAr, pbr, fmaf(-sAi, pbi, br));
            float nbi = fmaf(sAr, pbi, fmaf(sAi, pbr, bi));
            br = nbr; bi = nbi;
            float nAr = sAr * pAr - sAi * pAi;
            float nAi = sAr * pAi + sAi * pAr;
            sAr = nAr; sAi = nAi;
        }
    }

    // exclusive handoff: state entering this lane's segment = inclusive of lane-1
    float s0r = __shfl_up_sync(0xffffffffu, br, 1);
    float s0i = __shfl_up_sync(0xffffffffu, bi, 1);
    if (lane == 0) { s0r = 0.f; s0i = 0.f; }

    float sr = s0r, si = s0i;
#pragma unroll
    for (int j = 0; j < 4; j++) {
        int c = lane * 4 + j;
        g_Sre[c * H_DIM + h] = sr;
        g_Sim[c * H_DIM + h] = si;
        float er = g_Ere[c * H_DIM + h];
        float ei = g_Eim[c * H_DIM + h];
        float nr = fmaf(Ar, sr, fmaf(-Ai, si, er));
        float ni = fmaf(Ar, si, fmaf(Ai, sr, ei));
        sr = nr; si = ni;
    }
    if (lane == 31) {               // final state = hidden[-1]
        if (head_mode == 1) {
            out_head[h] = sr;
        } else if (head_mode == 2) {
            out_head[2 * h]     = sr;
            out_head[2 * h + 1] = si;
        }
    }
}

__global__ void scan_apply() {      // emits fp16 hidden state into g_Hh
    int i = blockIdx.x * blockDim.x + threadIdx.x;   // channel pair 0..511
    int c = blockIdx.y;
    int h = i * 2;
    float2 lre = *(float2*)&g_lre[h];
    float2 lim = *(float2*)&g_lim[h];
    float2 sr = *(float2*)&g_Sre[c * H_DIM + h];
    float2 si = *(float2*)&g_Sim[c * H_DIM + h];
    float hr0 = sr.x, hi0 = si.x, hr1 = sr.y, hi1 = si.y;
#pragma unroll 4
    for (int t = 0; t < T_CHUNK; t++) {
        size_t row = (size_t)(c * T_CHUNK + t) * 2048;
        float2 br = __half22float2(*(__half2*)&g_Buh[row + h]);
        float2 bi = __half22float2(*(__half2*)&g_Buh[row + 1024 + h]);
        float nr0 = fmaf(lre.x, hr0, fmaf(-lim.x, hi0, br.x));
        float ni0 = fmaf(lre.x, hi0, fmaf(lim.x, hr0, bi.x));
        float nr1 = fmaf(lre.y, hr1, fmaf(-lim.y, hi1, br.y));
        float ni1 = fmaf(lre.y, hi1, fmaf(lim.y, hr1, bi.y));
        hr0 = nr0; hi0 = ni0; hr1 = nr1; hi1 = ni1;
        *(__half2*)&g_Hh[row + h]        = __floats2half2_rn(hr0, hr1);
        *(__half2*)&g_Hh[row + 1024 + h] = __floats2half2_rn(hi0, hi1);
    }
}

// ---------------- launch ----------------
extern "C" void kernel_launch(void* const* d_in, const int* in_sizes, int n_in,
                              void* d_out, int out_size) {
    const float* x         = (const float*)d_in[0];
    const float* nu_log    = (const float*)d_in[1];
    const float* theta_log = (const float*)d_in[2];
    const float* gamma_log = (const float*)d_in[3];
    const float* Bre       = (const float*)d_in[4];
    const float* Bim       = (const float*)d_in[5];
    const float* Cre       = (const float*)d_in[6];
    const float* Cim       = (const float*)d_in[7];
    const float* Dp        = (const float*)d_in[8];

    float* out = (float*)d_out;
    long long head = (long long)out_size - (long long)L_SEQ * D_MOD;
    if (head < 0) head = 0;
    int head_mode = 0;
    if (head >= 2 * H_DIM)  head_mode = 2;
    else if (head >= H_DIM) head_mode = 1;
    float* out_head = out;
    float* out_y = out + head;

    __half *pxh, *pW1h, *pW2h, *pHh, *pBuh;
    cudaGetSymbolAddress((void**)&pxh,  g_xh);
    cudaGetSymbolAddress((void**)&pW1h, g_W1h);
    cudaGetSymbolAddress((void**)&pW2h, g_W2h);
    cudaGetSymbolAddress((void**)&pHh,  g_Hh);
    cudaGetSymbolAddress((void**)&pBuh, g_Buh);

    cudaFuncSetAttribute((const void*)mma_gemm<0,1>, cudaFuncAttributeMaxDynamicSharedMemorySize, SMEM_TOTAL);
    cudaFuncSetAttribute((const void*)mma_gemm<1,0>, cudaFuncAttributeMaxDynamicSharedMemorySize, SMEM_TOTAL);

    // launches 1-3 (prep), so GEMM1 is launch #4 (where ncu lands)
    prep_small<<<D_MOD + 4, 256>>>(Cre, Cim, nu_log, theta_log);
    prep_W1k<<<2 * H_DIM, 256>>>(Bre, Bim, gamma_log);
    conv_x<<<(L_SEQ * D_MOD) / (256 * 4), 256>>>(x);

    // GEMM1: Bu[16384 x 2048] (fp16) = x @ [B'_re ; B'_im]^T   (K=1024 halves)
    mma_gemm<0,1><<<dim3(L_SEQ / 128, 2048 / 128), 256, SMEM_TOTAL>>>(
        pxh, pW1h, pBuh, 1024, 2048, nullptr, nullptr);

    scan_chunks<<<dim3(H_DIM / 512, N_CHUNK), 256>>>();
    scan_combine<<<(H_DIM * 32) / 256, 256>>>(out_head, head_mode);   // 1 warp per channel
    scan_apply<<<dim3(H_DIM / 512, N_CHUNK), 256>>>();

    // GEMM2: y = [Hre|Him] @ [Cre|-Cim]^T + Dp*x   (K=2048 halves)
    mma_gemm<1,0><<<dim3(L_SEQ / 128, 1024 / 128), 256, SMEM_TOTAL>>>(
        pHh, pW2h, out_y, 2048, 1024, Dp, x);
}

// round 16
// speedup vs baseline: 1.2134x; 1.1324x over previous
#include <cuda_runtime.h>
#include <cuda_fp16.h>
#include <cstdint>

#define L_SEQ   16384
#define D_MOD   1024
#define H_DIM   1024
#define T_CHUNK 128
#define N_CHUNK 128   // L_SEQ / T_CHUNK

// ---------------- static scratch ----------------
__device__ __half g_xh [(size_t)L_SEQ * D_MOD];          // fp16 x
__device__ __half g_W1h[(size_t)2 * H_DIM * D_MOD];      // [2048 x 1024] stacked re/im of scaled B
__device__ __half g_W2h[(size_t)D_MOD * 2 * H_DIM];      // [1024 x 2048] = [Cre | -Cim]
__device__ __half g_Buh[(size_t)L_SEQ * 2 * H_DIM];      // [16384 x 2048] Bu fp16 (scan input)
__device__ __half g_Hh [(size_t)L_SEQ * 2 * H_DIM];      // [16384 x 2048] hidden re|im (fp16)
__device__ float g_lre[H_DIM], g_lim[H_DIM];
__device__ float g_lTre[H_DIM], g_lTim[H_DIM];
__device__ float g_Ere[N_CHUNK * H_DIM], g_Eim[N_CHUNK * H_DIM];
__device__ float g_Sre[N_CHUNK * H_DIM], g_Sim[N_CHUNK * H_DIM];

// ---------------- helpers ----------------
__device__ __forceinline__ void cp16(uint32_t dst, const void* src) {
    asm volatile("cp.async.cg.shared.global [%0], [%1], 16;" :: "r"(dst), "l"(src) : "memory");
}
__device__ __forceinline__ void cp_commit() { asm volatile("cp.async.commit_group;" ::: "memory"); }
__device__ __forceinline__ void cp_wait1()  { asm volatile("cp.async.wait_group 1;" ::: "memory"); }
__device__ __forceinline__ void cp_wait0()  { asm volatile("cp.async.wait_group 0;" ::: "memory"); }
__device__ __forceinline__ uint32_t smem_u32(const void* p) {
    uint32_t a;
    asm("{ .reg .u64 t; cvta.to.shared.u64 t, %1; cvt.u32.u64 %0, t; }" : "=r"(a) : "l"(p));
    return a;
}
// fp16 HMMA, fp32 accumulate: 4 A regs (8 halves), 2 B regs (4 halves)
__device__ __forceinline__ void mma_f16(float* c, uint32_t a0, uint32_t a1, uint32_t a2, uint32_t a3,
                                        uint32_t b0, uint32_t b1) {
    asm volatile(
        "mma.sync.aligned.m16n8k16.row.col.f32.f16.f16.f32 "
        "{%0,%1,%2,%3}, {%4,%5,%6,%7}, {%8,%9}, {%0,%1,%2,%3};\n"
        : "+f"(c[0]), "+f"(c[1]), "+f"(c[2]), "+f"(c[3])
        : "r"(a0), "r"(a1), "r"(a2), "r"(a3), "r"(b0), "r"(b1));
}

// smem tile: 128 rows x 64 halves (= 32 b32), row stride 36 b32 (conflict-free: 36 ≡ 4 mod 32)
#define TSTRIDE   36                         // in b32 units
#define TILE_U32  (128 * TSTRIDE)            // 4608 b32 = 18432 B
#define STAGE_U32 (2 * TILE_U32)             // A tile + B tile
#define SMEM_TOTAL (2 * STAGE_U32 * 4)       // double buffered = 73728 B; x2 CTAs = 147KB

// ---------------- FP16 NT GEMM: O[m,n] = sum_k A[m,k] * W[n,k]  (+ EPI: Dp[n]*X[m,n]) ----------------
// 128x128 block tile, BK=64 halves, 512 threads = 16 warps as 4(m) x 4(n); warp tile 32x32.
// Per-thread: 32 accum regs -> 2 CTAs/SM -> 32 warps/SM (50% occ).
// K, offsets in HALF units.  OUTH=1: store __half2 into a half buffer; else float2.
template <int EPI, int OUTH>
__global__ __launch_bounds__(512, 2) void mma_gemm(
    const __half* __restrict__ A, const __half* __restrict__ W,
    void* __restrict__ O, int K, int Nout,
    const float* __restrict__ Dp, const float* __restrict__ X)
{
    extern __shared__ uint32_t smem[];
    const uint32_t sbase = smem_u32(smem);
    const int tid = threadIdx.x;
    const int wid = tid >> 5, lane = tid & 31;
    const int g = lane >> 2, tig = lane & 3;
    const int wm = wid & 3, wn = wid >> 2;           // 4 x 4 warps; warp tile 32 x 32
    const int m0 = blockIdx.x * 128, n0 = blockIdx.y * 128;
    const int NC = K >> 6;                           // K chunks of 64 halves

    const int r_ld  = tid >> 2;                      // 0..127 (row loaded by this thread)
    const int c4_ld = (tid & 3) * 2;                 // 16B-chunk base; i-loop covers +0,+1

    auto load_chunk = [&](int stage, int kc) {
        const uint32_t sa = sbase + (uint32_t)(stage * STAGE_U32) * 4u;
        const uint32_t sb = sa + (uint32_t)TILE_U32 * 4u;
        const int kbase = kc * 64;                   // halves
#pragma unroll
        for (int i = 0; i < 2; i++) {
            int c4 = c4_ld + i;                      // 0..7 (16B chunks)
            uint32_t doff = (uint32_t)(r_ld * TSTRIDE + c4 * 4) * 4u;
            cp16(sa + doff, A + (size_t)(m0 + r_ld) * K + kbase + c4 * 8);
            cp16(sb + doff, W + (size_t)(n0 + r_ld) * K + kbase + c4 * 8);
        }
    };

    float acc[2][4][4];
#pragma unroll
    for (int mt = 0; mt < 2; mt++)
#pragma unroll
        for (int nt = 0; nt < 4; nt++)
#pragma unroll
            for (int q = 0; q < 4; q++) acc[mt][nt][q] = 0.f;

    load_chunk(0, 0);
    cp_commit();

    for (int kc = 0; kc < NC; kc++) {
        if (kc + 1 < NC) {
            load_chunk((kc + 1) & 1, kc + 1);
            cp_commit();
            cp_wait1();
        } else {
            cp_wait0();
        }
        __syncthreads();
        const uint32_t* As = smem + (kc & 1) * STAGE_U32;
        const uint32_t* Bs = As + TILE_U32;
#pragma unroll
        for (int s = 0; s < 4; s++) {                // 4 k16-steps; each = 8 b32
            const int k0 = s * 8;                    // b32 units
            uint32_t af[2][4];
#pragma unroll
            for (int mt = 0; mt < 2; mt++) {
                int r = wm * 32 + mt * 16 + g;
                af[mt][0] = As[r * TSTRIDE + k0 + tig];
                af[mt][1] = As[(r + 8) * TSTRIDE + k0 + tig];
                af[mt][2] = As[r * TSTRIDE + k0 + tig + 4];
                af[mt][3] = As[(r + 8) * TSTRIDE + k0 + tig + 4];
            }
            uint32_t bf[4][2];
#pragma unroll
            for (int nt = 0; nt < 4; nt++) {
                int n = wn * 32 + nt * 8 + g;
                bf[nt][0] = Bs[n * TSTRIDE + k0 + tig];
                bf[nt][1] = Bs[n * TSTRIDE + k0 + tig + 4];
            }
#pragma unroll
            for (int mt = 0; mt < 2; mt++)
#pragma unroll
                for (int nt = 0; nt < 4; nt++)
                    mma_f16(acc[mt][nt], af[mt][0], af[mt][1], af[mt][2], af[mt][3],
                            bf[nt][0], bf[nt][1]);
        }
        __syncthreads();
    }

    // epilogue
#pragma unroll
    for (int mt = 0; mt < 2; mt++) {
        int row0 = m0 + wm * 32 + mt * 16 + g;
#pragma unroll
        for (int nt = 0; nt < 4; nt++) {
            int col = n0 + wn * 32 + nt * 8 + tig * 2;
            float2 v0 = make_float2(acc[mt][nt][0], acc[mt][nt][1]);
            float2 v1 = make_float2(acc[mt][nt][2], acc[mt][nt][3]);
            if (EPI) {
                float2 dp = *(const float2*)(Dp + col);
                float2 x0 = *(const float2*)(X + (size_t)row0 * 1024 + col);
                float2 x1 = *(const float2*)(X + (size_t)(row0 + 8) * 1024 + col);
                v0.x += dp.x * x0.x; v0.y += dp.y * x0.y;
                v1.x += dp.x * x1.x; v1.y += dp.y * x1.y;
            }
            if (OUTH) {
                __half* Oh = (__half*)O;
                *(__half2*)(Oh + (size_t)row0 * Nout + col) = __floats2half2_rn(v0.x, v0.y);
                *(__half2*)(Oh + (size_t)(row0 + 8) * Nout + col) = __floats2half2_rn(v1.x, v1.y);
            } else {
                float* Of = (float*)O;
                *(float2*)(Of + (size_t)row0 * Nout + col) = v0;
                *(float2*)(Of + (size_t)(row0 + 8) * Nout + col) = v1;
            }
        }
    }
}

// ---------------- prep kernels (split so GEMM1 is the 4th launch for ncu capture) ----------------
// launch #1: params + W2
__global__ void prep_small(const float* __restrict__ Cre, const float* __restrict__ Cim,
                           const float* __restrict__ nu_log, const float* __restrict__ theta_log) {
    int b = blockIdx.x;
    if (b < D_MOD) {                 // W2 rows
        int n = b;
#pragma unroll
        for (int j = 0; j < 8; j++) {
            int k = threadIdx.x + j * 256;
            float v = (k < 1024) ? Cre[n * 1024 + k] : -Cim[n * 1024 + (k - 1024)];
            g_W2h[(size_t)n * 2048 + k] = __float2half_rn(v);
        }
        return;
    }
    b -= D_MOD;
    {   // params: 4 blocks
        int h = b * 256 + threadIdx.x;
        if (h >= H_DIM) return;
        float nu = expf(nu_log[h]);
        float th = expf(theta_log[h]);
        float mag = expf(-nu);
        float lre = mag * cosf(th);
        float lim = mag * sinf(th);
        g_lre[h] = lre; g_lim[h] = lim;
        float ar = 1.f, ai = 0.f;
        for (int t = 0; t < T_CHUNK; t++) {
            float nr = ar * lre - ai * lim;
            ai = ar * lim + ai * lre;
            ar = nr;
        }
        g_lTre[h] = ar; g_lTim[h] = ai;
    }
}

// launch #2: W1
__global__ void prep_W1k(const float* __restrict__ Bre, const float* __restrict__ Bim,
                         const float* __restrict__ gamma_log) {
    int n = blockIdx.x;             // 0..2047
    int h = n & 1023;
    const float* src = (n < 1024) ? Bre : Bim;
    float eg = expf(gamma_log[h]);
#pragma unroll
    for (int j = 0; j < 4; j++) {
        int k = threadIdx.x * 4 + j;
        g_W1h[(size_t)n * 1024 + k] = __float2half_rn(src[h * 1024 + k] * eg);
    }
}

// launch #3: x -> fp16
__global__ void conv_x(const float* __restrict__ x) {
    size_t i = (size_t)(blockIdx.x * blockDim.x + threadIdx.x) * 4;
    float4 v = *(const float4*)(x + i);
    g_xh[i + 0] = __float2half_rn(v.x);
    g_xh[i + 1] = __float2half_rn(v.y);
    g_xh[i + 2] = __float2half_rn(v.z);
    g_xh[i + 3] = __float2half_rn(v.w);
}

// ---------------- scan (stacked [L x 2048]: re | im), 2 channels per thread ----------------
__global__ void scan_chunks() {
    int i = blockIdx.x * blockDim.x + threadIdx.x;   // channel pair 0..511
    int c = blockIdx.y;
    int h = i * 2;
    float2 lre = *(float2*)&g_lre[h];
    float2 lim = *(float2*)&g_lim[h];
    float hr0 = 0.f, hi0 = 0.f, hr1 = 0.f, hi1 = 0.f;
#pragma unroll 4
    for (int t = 0; t < T_CHUNK; t++) {
        size_t row = (size_t)(c * T_CHUNK + t) * 2048;
        float2 br = __half22float2(*(__half2*)&g_Buh[row + h]);
        float2 bi = __half22float2(*(__half2*)&g_Buh[row + 1024 + h]);
        float nr0 = fmaf(lre.x, hr0, fmaf(-lim.x, hi0, br.x));
        float ni0 = fmaf(lre.x, hi0, fmaf(lim.x, hr0, bi.x));
        float nr1 = fmaf(lre.y, hr1, fmaf(-lim.y, hi1, br.y));
        float ni1 = fmaf(lre.y, hi1, fmaf(lim.y, hr1, bi.y));
        hr0 = nr0; hi0 = ni0; hr1 = nr1; hi1 = ni1;
    }
    *(float2*)&g_Ere[c * H_DIM + h] = make_float2(hr0, hr1);
    *(float2*)&g_Eim[c * H_DIM + h] = make_float2(hi0, hi1);
}

// ---------------- cross-chunk scan: warp-parallel Kogge-Stone, one warp per channel ----------------
__global__ void scan_combine(float* __restrict__ out_head, int head_mode) {
    int h    = (blockIdx.x * blockDim.x + threadIdx.x) >> 5;  // channel = warp id
    int lane = threadIdx.x & 31;
    float Ar = g_lTre[h], Ai = g_lTim[h];      // λ^T_CHUNK (per-chunk multiplier)

    // local fold of 4 chunks (c = lane*4 + j): inclusive b over own segment
    float br = 0.f, bi = 0.f;
#pragma unroll
    for (int j = 0; j < 4; j++) {
        int c = lane * 4 + j;
        float er = g_Ere[c * H_DIM + h];
        float ei = g_Eim[c * H_DIM + h];
        float nr = fmaf(Ar, br, fmaf(-Ai, bi, er));
        float ni = fmaf(Ar, bi, fmaf(Ai, br, ei));
        br = nr; bi = ni;
    }
    // segment operator A_seg = λT^4 (two squarings)
    float A2r = Ar * Ar - Ai * Ai, A2i = 2.f * Ar * Ai;
    float sAr = A2r * A2r - A2i * A2i, sAi = 2.f * A2r * A2i;

    // Kogge-Stone inclusive scan over lanes with op (A_j*A_i, A_j*b_i + b_j)
#pragma unroll
    for (int d = 1; d < 32; d <<= 1) {
        float pAr = __shfl_up_sync(0xffffffffu, sAr, d);
        float pAi = __shfl_up_sync(0xffffffffu, sAi, d);
        float pbr = __shfl_up_sync(0xffffffffu, br, d);
        float pbi = __shfl_up_sync(0xffffffffu, bi, d);
        if (lane >= d) {
            float nbr = fmaf(sAr, pbr, fmaf(-sAi, pbi, br));
            float nbi = fmaf(sAr, pbi, fmaf(sAi, pbr, bi));
            br = nbr; bi = nbi;
            float nAr = sAr * pAr - sAi * pAi;
            float nAi = sAr * pAi + sAi * pAr;
            sAr = nAr; sAi = nAi;
        }
    }

    // exclusive handoff: state entering this lane's segment = inclusive of lane-1
    float s0r = __shfl_up_sync(0xffffffffu, br, 1);
    float s0i = __shfl_up_sync(0xffffffffu, bi, 1);
    if (lane == 0) { s0r = 0.f; s0i = 0.f; }

    float sr = s0r, si = s0i;
#pragma unroll
    for (int j = 0; j < 4; j++) {
        int c = lane * 4 + j;
        g_Sre[c * H_DIM + h] = sr;
        g_Sim[c * H_DIM + h] = si;
        float er = g_Ere[c * H_DIM + h];
        float ei = g_Eim[c * H_DIM + h];
        float nr = fmaf(Ar, sr, fmaf(-Ai, si, er));
        float ni = fmaf(Ar, si, fmaf(Ai, sr, ei));
        sr = nr; si = ni;
    }
    if (lane == 31) {               // final state = hidden[-1]
        if (head_mode == 1) {
            out_head[h] = sr;
        } else if (head_mode == 2) {
            out_head[2 * h]     = sr;
            out_head[2 * h + 1] = si;
        }
    }
}

__global__ void scan_apply() {      // emits fp16 hidden state into g_Hh
    int i = blockIdx.x * blockDim.x + threadIdx.x;   // channel pair 0..511
    int c = blockIdx.y;
    int h = i * 2;
    float2 lre = *(float2*)&g_lre[h];
    float2 lim = *(float2*)&g_lim[h];
    float2 sr = *(float2*)&g_Sre[c * H_DIM + h];
    float2 si = *(float2*)&g_Sim[c * H_DIM + h];
    float hr0 = sr.x, hi0 = si.x, hr1 = sr.y, hi1 = si.y;
#pragma unroll 4
    for (int t = 0; t < T_CHUNK; t++) {
        size_t row = (size_t)(c * T_CHUNK + t) * 2048;
        float2 br = __half22float2(*(__half2*)&g_Buh[row + h]);
        float2 bi = __half22float2(*(__half2*)&g_Buh[row + 1024 + h]);
        float nr0 = fmaf(lre.x, hr0, fmaf(-lim.x, hi0, br.x));
        float ni0 = fmaf(lre.x, hi0, fmaf(lim.x, hr0, bi.x));
        float nr1 = fmaf(lre.y, hr1, fmaf(-lim.y, hi1, br.y));
        float ni1 = fmaf(lre.y, hi1, fmaf(lim.y, hr1, bi.y));
        hr0 = nr0; hi0 = ni0; hr1 = nr1; hi1 = ni1;
        *(__half2*)&g_Hh[row + h]        = __floats2half2_rn(hr0, hr1);
        *(__half2*)&g_Hh[row + 1024 + h] = __floats2half2_rn(hi0, hi1);
    }
}

// ---------------- launch ----------------
extern "C" void kernel_launch(void* const* d_in, const int* in_sizes, int n_in,
                              void* d_out, int out_size) {
    const float* x         = (const float*)d_in[0];
    const float* nu_log    = (const float*)d_in[1];
    const float* theta_log = (const float*)d_in[2];
    const float* gamma_log = (const float*)d_in[3];
    const float* Bre       = (const float*)d_in[4];
    const float* Bim       = (const float*)d_in[5];
    const float* Cre       = (const float*)d_in[6];
    const float* Cim       = (const float*)d_in[7];
    const float* Dp        = (const float*)d_in[8];

    float* out = (float*)d_out;
    long long head = (long long)out_size - (long long)L_SEQ * D_MOD;
    if (head < 0) head = 0;
    int head_mode = 0;
    if (head >= 2 * H_DIM)  head_mode = 2;
    else if (head >= H_DIM) head_mode = 1;
    float* out_head = out;
    float* out_y = out + head;

    __half *pxh, *pW1h, *pW2h, *pHh, *pBuh;
    cudaGetSymbolAddress((void**)&pxh,  g_xh);
    cudaGetSymbolAddress((void**)&pW1h, g_W1h);
    cudaGetSymbolAddress((void**)&pW2h, g_W2h);
    cudaGetSymbolAddress((void**)&pHh,  g_Hh);
    cudaGetSymbolAddress((void**)&pBuh, g_Buh);

    cudaFuncSetAttribute((const void*)mma_gemm<0,1>, cudaFuncAttributeMaxDynamicSharedMemorySize, SMEM_TOTAL);
    cudaFuncSetAttribute((const void*)mma_gemm<1,0>, cudaFuncAttributeMaxDynamicSharedMemorySize, SMEM_TOTAL);

    // launches 1-3 (prep), so GEMM1 is launch #4 (where ncu lands)
    prep_small<<<D_MOD + 4, 256>>>(Cre, Cim, nu_log, theta_log);
    prep_W1k<<<2 * H_DIM, 256>>>(Bre, Bim, gamma_log);
    conv_x<<<(L_SEQ * D_MOD) / (256 * 4), 256>>>(x);

    // GEMM1: Bu[16384 x 2048] (fp16) = x @ [B'_re ; B'_im]^T   (K=1024 halves)
    mma_gemm<0,1><<<dim3(L_SEQ / 128, 2048 / 128), 512, SMEM_TOTAL>>>(
        pxh, pW1h, pBuh, 1024, 2048, nullptr, nullptr);

    scan_chunks<<<dim3(H_DIM / 512, N_CHUNK), 256>>>();
    scan_combine<<<(H_DIM * 32) / 256, 256>>>(out_head, head_mode);   // 1 warp per channel
    scan_apply<<<dim3(H_DIM / 512, N_CHUNK), 256>>>();

    // GEMM2: y = [Hre|Him] @ [Cre|-Cim]^T + Dp*x   (K=2048 halves)
    mma_gemm<1,0><<<dim3(L_SEQ / 128, 1024 / 128), 512, SMEM_TOTAL>>>(
        pHh, pW2h, out_y, 2048, 1024, Dp, x);
}

// round 17
// speedup vs baseline: 1.3866x; 1.1428x over previous
#include <cuda_runtime.h>
#include <cuda_fp16.h>
#include <cstdint>

#define L_SEQ   16384
#define D_MOD   1024
#define H_DIM   1024
#define T_CHUNK 128
#define N_CHUNK 128   // L_SEQ / T_CHUNK

// ---------------- static scratch ----------------
__device__ __half g_xh [(size_t)L_SEQ * D_MOD];          // fp16 x
__device__ __half g_W1h[(size_t)2 * H_DIM * D_MOD];      // [2048 x 1024] stacked re/im of scaled B
__device__ __half g_W2h[(size_t)D_MOD * 2 * H_DIM];      // [1024 x 2048] = [Cre | -Cim]
__device__ __half g_Buh[(size_t)L_SEQ * 2 * H_DIM];      // [16384 x 2048] Bu fp16 (scan input)
__device__ __half g_Hh [(size_t)L_SEQ * 2 * H_DIM];      // [16384 x 2048] hidden re|im (fp16)
__device__ float g_lre[H_DIM], g_lim[H_DIM];
__device__ float g_lTre[H_DIM], g_lTim[H_DIM];
__device__ float g_Ere[N_CHUNK * H_DIM], g_Eim[N_CHUNK * H_DIM];
__device__ float g_Sre[N_CHUNK * H_DIM], g_Sim[N_CHUNK * H_DIM];

// ---------------- helpers ----------------
__device__ __forceinline__ void cp16(uint32_t dst, const void* src) {
    asm volatile("cp.async.cg.shared.global [%0], [%1], 16;" :: "r"(dst), "l"(src) : "memory");
}
__device__ __forceinline__ void cp_commit() { asm volatile("cp.async.commit_group;" ::: "memory"); }
__device__ __forceinline__ void cp_wait1()  { asm volatile("cp.async.wait_group 1;" ::: "memory"); }
__device__ __forceinline__ void cp_wait0()  { asm volatile("cp.async.wait_group 0;" ::: "memory"); }
__device__ __forceinline__ uint32_t smem_u32(const void* p) {
    uint32_t a;
    asm("{ .reg .u64 t; cvta.to.shared.u64 t, %1; cvt.u32.u64 %0, t; }" : "=r"(a) : "l"(p));
    return a;
}
// fp16 HMMA, fp32 accumulate: 4 A regs (8 halves), 2 B regs (4 halves)
__device__ __forceinline__ void mma_f16(float* c, uint32_t a0, uint32_t a1, uint32_t a2, uint32_t a3,
                                        uint32_t b0, uint32_t b1) {
    asm volatile(
        "mma.sync.aligned.m16n8k16.row.col.f32.f16.f16.f32 "
        "{%0,%1,%2,%3}, {%4,%5,%6,%7}, {%8,%9}, {%0,%1,%2,%3};\n"
        : "+f"(c[0]), "+f"(c[1]), "+f"(c[2]), "+f"(c[3])
        : "r"(a0), "r"(a1), "r"(a2), "r"(a3), "r"(b0), "r"(b1));
}
// ldmatrix x4: four 8x8-b16 tiles; reg j = tile j, thread t <- (row t/4, b32 col t%4)
__device__ __forceinline__ void ldsm4(uint32_t* r, uint32_t addr) {
    asm volatile("ldmatrix.sync.aligned.m8n8.x4.shared.b16 {%0,%1,%2,%3}, [%4];"
                 : "=r"(r[0]), "=r"(r[1]), "=r"(r[2]), "=r"(r[3]) : "r"(addr));
}

// smem tile: 128 rows x 64 halves (= 32 b32), row stride 36 b32 (conflict-free: 36 ≡ 4 mod 32)
#define TSTRIDE   36                         // in b32 units
#define TILE_U32  (128 * TSTRIDE)            // 4608 b32 = 18432 B
#define STAGE_U32 (2 * TILE_U32)             // A tile + B tile
#define SMEM_TOTAL (2 * STAGE_U32 * 4)       // double buffered = 73728 B; x2 CTAs = 147KB

// ---------------- FP16 NT GEMM: O[m,n] = sum_k A[m,k] * W[n,k]  (+ EPI: Dp[n]*X[m,n]) ----------------
// 128x128 block tile, BK=64 halves, 512 threads = 16 warps as 4(m) x 4(n); warp tile 32x32.
// Fragments fed by ldmatrix.x4 (4 instr/step instead of 16 scalar LDS).
// K, offsets in HALF units.  OUTH=1: store __half2 into a half buffer; else float2.
template <int EPI, int OUTH>
__global__ __launch_bounds__(512, 2) void mma_gemm(
    const __half* __restrict__ A, const __half* __restrict__ W,
    void* __restrict__ O, int K, int Nout,
    const float* __restrict__ Dp, const float* __restrict__ X)
{
    extern __shared__ uint32_t smem[];
    const uint32_t sbase = smem_u32(smem);
    const int tid = threadIdx.x;
    const int wid = tid >> 5, lane = tid & 31;
    const int g = lane >> 2, tig = lane & 3;
    const int wm = wid & 3, wn = wid >> 2;           // 4 x 4 warps; warp tile 32 x 32
    const int m0 = blockIdx.x * 128, n0 = blockIdx.y * 128;
    const int NC = K >> 6;                           // K chunks of 64 halves

    const int r_ld  = tid >> 2;                      // 0..127 (row loaded by this thread)
    const int c4_ld = (tid & 3) * 2;                 // 16B-chunk base; i-loop covers +0,+1

    auto load_chunk = [&](int stage, int kc) {
        const uint32_t sa = sbase + (uint32_t)(stage * STAGE_U32) * 4u;
        const uint32_t sb = sa + (uint32_t)TILE_U32 * 4u;
        const int kbase = kc * 64;                   // halves
#pragma unroll
        for (int i = 0; i < 2; i++) {
            int c4 = c4_ld + i;                      // 0..7 (16B chunks)
            uint32_t doff = (uint32_t)(r_ld * TSTRIDE + c4 * 4) * 4u;
            cp16(sa + doff, A + (size_t)(m0 + r_ld) * K + kbase + c4 * 8);
            cp16(sb + doff, W + (size_t)(n0 + r_ld) * K + kbase + c4 * 8);
        }
    };

    // per-lane ldmatrix base offsets (bytes, within a stage)
    // A tiles for warp-tile mt: j0=(+0r,k0) j1=(+8r,k0) j2=(+0r,k0+4) j3=(+8r,k0+4)
    //   lane group lj: lj&1 -> +8 rows, lj>>1 -> +4 b32 cols
    const int lrow = lane & 7, lj = lane >> 3;
    const uint32_t a_off = (uint32_t)(((wm * 32 + (lj & 1) * 8 + lrow) * TSTRIDE
                                       + (lj >> 1) * 4) * 4);
    // B tiles for nt-pair p: j0=(nt=2p,k0) j1=(nt=2p,k0+4) j2=(nt=2p+1,k0) j3=(nt=2p+1,k0+4)
    //   lane group lj: lj>>1 -> +8 rows (nt), lj&1 -> +4 b32 cols
    const uint32_t b_off = (uint32_t)(TILE_U32 * 4
                                      + ((wn * 32 + (lj >> 1) * 8 + lrow) * TSTRIDE
                                         + (lj & 1) * 4) * 4);

    float acc[2][4][4];
#pragma unroll
    for (int mt = 0; mt < 2; mt++)
#pragma unroll
        for (int nt = 0; nt < 4; nt++)
#pragma unroll
            for (int q = 0; q < 4; q++) acc[mt][nt][q] = 0.f;

    load_chunk(0, 0);
    cp_commit();

    for (int kc = 0; kc < NC; kc++) {
        if (kc + 1 < NC) {
            load_chunk((kc + 1) & 1, kc + 1);
            cp_commit();
            cp_wait1();
        } else {
            cp_wait0();
        }
        __syncthreads();
        const uint32_t st4 = sbase + (uint32_t)((kc & 1) * STAGE_U32) * 4u;
#pragma unroll
        for (int s = 0; s < 4; s++) {                // 4 k16-steps; each = 8 b32
            const uint32_t koff = (uint32_t)(s * 8 * 4);       // 8 b32 in bytes
            uint32_t af[2][4];
            ldsm4(af[0], st4 + a_off + koff);
            ldsm4(af[1], st4 + a_off + (uint32_t)(16 * TSTRIDE * 4) + koff);
            uint32_t bf[2][4];                       // [p][ (nt&1)*2 + reg ]
            ldsm4(bf[0], st4 + b_off + koff);
            ldsm4(bf[1], st4 + b_off + (uint32_t)(16 * TSTRIDE * 4) + koff);
#pragma unroll
            for (int mt = 0; mt < 2; mt++)
#pragma unroll
                for (int nt = 0; nt < 4; nt++)
                    mma_f16(acc[mt][nt], af[mt][0], af[mt][1], af[mt][2], af[mt][3],
                            bf[nt >> 1][(nt & 1) * 2], bf[nt >> 1][(nt & 1) * 2 + 1]);
        }
        __syncthreads();
    }

    // epilogue
#pragma unroll
    for (int mt = 0; mt < 2; mt++) {
        int row0 = m0 + wm * 32 + mt * 16 + g;
#pragma unroll
        for (int nt = 0; nt < 4; nt++) {
            int col = n0 + wn * 32 + nt * 8 + tig * 2;
            float2 v0 = make_float2(acc[mt][nt][0], acc[mt][nt][1]);
            float2 v1 = make_float2(acc[mt][nt][2], acc[mt][nt][3]);
            if (EPI) {
                float2 dp = *(const float2*)(Dp + col);
                float2 x0 = *(const float2*)(X + (size_t)row0 * 1024 + col);
                float2 x1 = *(const float2*)(X + (size_t)(row0 + 8) * 1024 + col);
                v0.x += dp.x * x0.x; v0.y += dp.y * x0.y;
                v1.x += dp.x * x1.x; v1.y += dp.y * x1.y;
            }
            if (OUTH) {
                __half* Oh = (__half*)O;
                *(__half2*)(Oh + (size_t)row0 * Nout + col) = __floats2half2_rn(v0.x, v0.y);
                *(__half2*)(Oh + (size_t)(row0 + 8) * Nout + col) = __floats2half2_rn(v1.x, v1.y);
            } else {
                float* Of = (float*)O;
                *(float2*)(Of + (size_t)row0 * Nout + col) = v0;
                *(float2*)(Of + (size_t)(row0 + 8) * Nout + col) = v1;
            }
        }
    }
}

// ---------------- prep kernels (split so GEMM1 is the 4th launch for ncu capture) ----------------
// launch #1: params + W2
__global__ void prep_small(const float* __restrict__ Cre, const float* __restrict__ Cim,
                           const float* __restrict__ nu_log, const float* __restrict__ theta_log) {
    int b = blockIdx.x;
    if (b < D_MOD) {                 // W2 rows
        int n = b;
#pragma unroll
        for (int j = 0; j < 8; j++) {
            int k = threadIdx.x + j * 256;
            float v = (k < 1024) ? Cre[n * 1024 + k] : -Cim[n * 1024 + (k - 1024)];
            g_W2h[(size_t)n * 2048 + k] = __float2half_rn(v);
        }
        return;
    }
    b -= D_MOD;
    {   // params: 4 blocks
        int h = b * 256 + threadIdx.x;
        if (h >= H_DIM) return;
        float nu = expf(nu_log[h]);
        float th = expf(theta_log[h]);
        float mag = expf(-nu);
        float lre = mag * cosf(th);
        float lim = mag * sinf(th);
        g_lre[h] = lre; g_lim[h] = lim;
        float ar = 1.f, ai = 0.f;
        for (int t = 0; t < T_CHUNK; t++) {
            float nr = ar * lre - ai * lim;
            ai = ar * lim + ai * lre;
            ar = nr;
        }
        g_lTre[h] = ar; g_lTim[h] = ai;
    }
}

// launch #2: W1
__global__ void prep_W1k(const float* __restrict__ Bre, const float* __restrict__ Bim,
                         const float* __restrict__ gamma_log) {
    int n = blockIdx.x;             // 0..2047
    int h = n & 1023;
    const float* src = (n < 1024) ? Bre : Bim;
    float eg = expf(gamma_log[h]);
#pragma unroll
    for (int j = 0; j < 4; j++) {
        int k = threadIdx.x * 4 + j;
        g_W1h[(size_t)n * 1024 + k] = __float2half_rn(src[h * 1024 + k] * eg);
    }
}

// launch #3: x -> fp16
__global__ void conv_x(const float* __restrict__ x) {
    size_t i = (size_t)(blockIdx.x * blockDim.x + threadIdx.x) * 4;
    float4 v = *(const float4*)(x + i);
    g_xh[i + 0] = __float2half_rn(v.x);
    g_xh[i + 1] = __float2half_rn(v.y);
    g_xh[i + 2] = __float2half_rn(v.z);
    g_xh[i + 3] = __float2half_rn(v.w);
}

// ---------------- scan (stacked [L x 2048]: re | im), 2 channels per thread ----------------
__global__ void scan_chunks() {
    int i = blockIdx.x * blockDim.x + threadIdx.x;   // channel pair 0..511
    int c = blockIdx.y;
    int h = i * 2;
    float2 lre = *(float2*)&g_lre[h];
    float2 lim = *(float2*)&g_lim[h];
    float hr0 = 0.f, hi0 = 0.f, hr1 = 0.f, hi1 = 0.f;
#pragma unroll 4
    for (int t = 0; t < T_CHUNK; t++) {
        size_t row = (size_t)(c * T_CHUNK + t) * 2048;
        float2 br = __half22float2(*(__half2*)&g_Buh[row + h]);
        float2 bi = __half22float2(*(__half2*)&g_Buh[row + 1024 + h]);
        float nr0 = fmaf(lre.x, hr0, fmaf(-lim.x, hi0, br.x));
        float ni0 = fmaf(lre.x, hi0, fmaf(lim.x, hr0, bi.x));
        float nr1 = fmaf(lre.y, hr1, fmaf(-lim.y, hi1, br.y));
        float ni1 = fmaf(lre.y, hi1, fmaf(lim.y, hr1, bi.y));
        hr0 = nr0; hi0 = ni0; hr1 = nr1; hi1 = ni1;
    }
    *(float2*)&g_Ere[c * H_DIM + h] = make_float2(hr0, hr1);
    *(float2*)&g_Eim[c * H_DIM + h] = make_float2(hi0, hi1);
}

// ---------------- cross-chunk scan: warp-parallel Kogge-Stone, one warp per channel ----------------
__global__ void scan_combine(float* __restrict__ out_head, int head_mode) {
    int h    = (blockIdx.x * blockDim.x + threadIdx.x) >> 5;  // channel = warp id
    int lane = threadIdx.x & 31;
    float Ar = g_lTre[h], Ai = g_lTim[h];      // λ^T_CHUNK (per-chunk multiplier)

    // local fold of 4 chunks (c = lane*4 + j): inclusive b over own segment
    float br = 0.f, bi = 0.f;
#pragma unroll
    for (int j = 0; j < 4; j++) {
        int c = lane * 4 + j;
        float er = g_Ere[c * H_DIM + h];
        float ei = g_Eim[c * H_DIM + h];
        float nr = fmaf(Ar, br, fmaf(-Ai, bi, er));
        float ni = fmaf(Ar, bi, fmaf(Ai, br, ei));
        br = nr; bi = ni;
    }
    // segment operator A_seg = λT^4 (two squarings)
    float A2r = Ar * Ar - Ai * Ai, A2i = 2.f * Ar * Ai;
    float sAr = A2r * A2r - A2i * A2i, sAi = 2.f * A2r * A2i;

    // Kogge-Stone inclusive scan over lanes with op (A_j*A_i, A_j*b_i + b_j)
#pragma unroll
    for (int d = 1; d < 32; d <<= 1) {
        float pAr = __shfl_up_sync(0xffffffffu, sAr, d);
        float pAi = __shfl_up_sync(0xffffffffu, sAi, d);
        float pbr = __shfl_up_sync(0xffffffffu, br, d);
        float pbi = __shfl_up_sync(0xffffffffu, bi, d);
        if (lane >= d) {
            float nbr = fmaf(sAr, pbr, fmaf(-sAi, pbi, br));
            float nbi = fmaf(sAr, pbi, fmaf(sAi, pbr, bi));
            br = nbr; bi = nbi;
            float nAr = sAr * pAr - sAi * pAi;
            float nAi = sAr * pAi + sAi * pAr;
            sAr = nAr; sAi = nAi;
        }
    }

    // exclusive handoff: state entering this lane's segment = inclusive of lane-1
    float s0r = __shfl_up_sync(0xffffffffu, br, 1);
    float s0i = __shfl_up_sync(0xffffffffu, bi, 1);
    if (lane == 0) { s0r = 0.f; s0i = 0.f; }

    float sr = s0r, si = s0i;
#pragma unroll
    for (int j = 0; j < 4; j++) {
        int c = lane * 4 + j;
        g_Sre[c * H_DIM + h] = sr;
        g_Sim[c * H_DIM + h] = si;
        float er = g_Ere[c * H_DIM + h];
        float ei = g_Eim[c * H_DIM + h];
        float nr = fmaf(Ar, sr, fmaf(-Ai, si, er));
        float ni = fmaf(Ar, si, fmaf(Ai, sr, ei));
        sr = nr; si = ni;
    }
    if (lane == 31) {               // final state = hidden[-1]
        if (head_mode == 1) {
            out_head[h] = sr;
        } else if (head_mode == 2) {
            out_head[2 * h]     = sr;
            out_head[2 * h + 1] = si;
        }
    }
}

__global__ void scan_apply() {      // emits fp16 hidden state into g_Hh
    int i = blockIdx.x * blockDim.x + threadIdx.x;   // channel pair 0..511
    int c = blockIdx.y;
    int h = i * 2;
    float2 lre = *(float2*)&g_lre[h];
    float2 lim = *(float2*)&g_lim[h];
    float2 sr = *(float2*)&g_Sre[c * H_DIM + h];
    float2 si = *(float2*)&g_Sim[c * H_DIM + h];
    float hr0 = sr.x, hi0 = si.x, hr1 = sr.y, hi1 = si.y;
#pragma unroll 4
    for (int t = 0; t < T_CHUNK; t++) {
        size_t row = (size_t)(c * T_CHUNK + t) * 2048;
        float2 br = __half22float2(*(__half2*)&g_Buh[row + h]);
        float2 bi = __half22float2(*(__half2*)&g_Buh[row + 1024 + h]);
        float nr0 = fmaf(lre.x, hr0, fmaf(-lim.x, hi0, br.x));
        float ni0 = fmaf(lre.x, hi0, fmaf(lim.x, hr0, bi.x));
        float nr1 = fmaf(lre.y, hr1, fmaf(-lim.y, hi1, br.y));
        float ni1 = fmaf(lre.y, hi1, fmaf(lim.y, hr1, bi.y));
        hr0 = nr0; hi0 = ni0; hr1 = nr1; hi1 = ni1;
        *(__half2*)&g_Hh[row + h]        = __floats2half2_rn(hr0, hr1);
        *(__half2*)&g_Hh[row + 1024 + h] = __floats2half2_rn(hi0, hi1);
    }
}

// ---------------- launch ----------------
extern "C" void kernel_launch(void* const* d_in, const int* in_sizes, int n_in,
                              void* d_out, int out_size) {
    const float* x         = (const float*)d_in[0];
    const float* nu_log    = (const float*)d_in[1];
    const float* theta_log = (const float*)d_in[2];
    const float* gamma_log = (const float*)d_in[3];
    const float* Bre       = (const float*)d_in[4];
    const float* Bim       = (const float*)d_in[5];
    const float* Cre       = (const float*)d_in[6];
    const float* Cim       = (const float*)d_in[7];
    const float* Dp        = (const float*)d_in[8];

    float* out = (float*)d_out;
    long long head = (long long)out_size - (long long)L_SEQ * D_MOD;
    if (head < 0) head = 0;
    int head_mode = 0;
    if (head >= 2 * H_DIM)  head_mode = 2;
    else if (head >= H_DIM) head_mode = 1;
    float* out_head = out;
    float* out_y = out + head;

    __half *pxh, *pW1h, *pW2h, *pHh, *pBuh;
    cudaGetSymbolAddress((void**)&pxh,  g_xh);
    cudaGetSymbolAddress((void**)&pW1h, g_W1h);
    cudaGetSymbolAddress((void**)&pW2h, g_W2h);
    cudaGetSymbolAddress((void**)&pHh,  g_Hh);
    cudaGetSymbolAddress((void**)&pBuh, g_Buh);

    cudaFuncSetAttribute((const void*)mma_gemm<0,1>, cudaFuncAttributeMaxDynamicSharedMemorySize, SMEM_TOTAL);
    cudaFuncSetAttribute((const void*)mma_gemm<1,0>, cudaFuncAttributeMaxDynamicSharedMemorySize, SMEM_TOTAL);

    // launches 1-3 (prep), so GEMM1 is launch #4 (where ncu lands)
    prep_small<<<D_MOD + 4, 256>>>(Cre, Cim, nu_log, theta_log);
    prep_W1k<<<2 * H_DIM, 256>>>(Bre, Bim, gamma_log);
    conv_x<<<(L_SEQ * D_MOD) / (256 * 4), 256>>>(x);

    // GEMM1: Bu[16384 x 2048] (fp16) = x @ [B'_re ; B'_im]^T   (K=1024 halves)
    mma_gemm<0,1><<<dim3(L_SEQ / 128, 2048 / 128), 512, SMEM_TOTAL>>>(
        pxh, pW1h, pBuh, 1024, 2048, nullptr, nullptr);

    scan_chunks<<<dim3(H_DIM / 512, N_CHUNK), 256>>>();
    scan_combine<<<(H_DIM * 32) / 256, 256>>>(out_head, head_mode);   // 1 warp per channel
    scan_apply<<<dim3(H_DIM / 512, N_CHUNK), 256>>>();

    // GEMM2: y = [Hre|Him] @ [Cre|-Cim]^T + Dp*x   (K=2048 halves)
    mma_gemm<1,0><<<dim3(L_SEQ / 128, 1024 / 128), 512, SMEM_TOTAL>>>(
        pHh, pW2h, out_y, 2048, 1024, Dp, x);
}